// round 2
// baseline (speedup 1.0000x reference)
#include <cuda_runtime.h>

#define S_LEN  2048
#define DMODEL 1024
#define BATCH  2
#define M_TOT  (BATCH * S_LEN)   // 4096
#define NHEAD  16
#define DHEAD  64

// Scratch (device globals — no allocation in kernel_launch)
__device__ float g_Q[M_TOT * DMODEL];
__device__ float g_K[M_TOT * DMODEL];
__device__ float g_V[M_TOT * DMODEL];
__device__ float g_CTX[M_TOT * DMODEL];

// ---------------------------------------------------------------------------
// GEMM: C[M_TOT, 1024] = A[M_TOT, 1024] @ B[1024, 1024] + bias
// BM=BN=64, BK=16, 256 threads, 4x4 register microtile per thread.
// ---------------------------------------------------------------------------
__global__ __launch_bounds__(256) void gemm_bias_kernel(
    const float* __restrict__ A, const float* __restrict__ B,
    const float* __restrict__ bias, float* __restrict__ C) {
  const int N = DMODEL, K = DMODEL;
  __shared__ float As[16][64];   // As[k][m]
  __shared__ float Bs[16][64];   // Bs[k][n]

  const int tid = threadIdx.x;
  const int tx = tid & 15;       // 0..15 -> n group
  const int ty = tid >> 4;       // 0..15 -> m group
  const int row0 = blockIdx.y << 6;
  const int col0 = blockIdx.x << 6;

  const int am = tid >> 2;            // 0..63
  const int ak = (tid & 3) << 2;      // 0,4,8,12
  const int bk = tid >> 4;            // 0..15
  const int bn = (tid & 15) << 2;     // 0..60

  const float* Ap = A + (size_t)(row0 + am) * K + ak;
  const float* Bp = B + (size_t)bk * N + col0 + bn;

  float acc[4][4] = {};

  for (int k0 = 0; k0 < K; k0 += 16) {
    float4 av = *(const float4*)(Ap + k0);
    float4 bv = *(const float4*)(Bp + (size_t)k0 * N);
    As[ak + 0][am] = av.x;
    As[ak + 1][am] = av.y;
    As[ak + 2][am] = av.z;
    As[ak + 3][am] = av.w;
    *(float4*)&Bs[bk][bn] = bv;
    __syncthreads();

#pragma unroll
    for (int k = 0; k < 16; k++) {
      float4 a = *(const float4*)&As[k][ty << 2];
      float4 b = *(const float4*)&Bs[k][tx << 2];
      float avr[4] = {a.x, a.y, a.z, a.w};
      float bvr[4] = {b.x, b.y, b.z, b.w};
#pragma unroll
      for (int i = 0; i < 4; i++)
#pragma unroll
        for (int j = 0; j < 4; j++)
          acc[i][j] += avr[i] * bvr[j];
    }
    __syncthreads();
  }

  float4 bb = *(const float4*)&bias[col0 + (tx << 2)];
  float bbr[4] = {bb.x, bb.y, bb.z, bb.w};
#pragma unroll
  for (int i = 0; i < 4; i++) {
    float4 v = make_float4(acc[i][0] + bbr[0], acc[i][1] + bbr[1],
                           acc[i][2] + bbr[2], acc[i][3] + bbr[3]);
    *(float4*)&C[(size_t)(row0 + (ty << 2) + i) * N + col0 + (tx << 2)] = v;
  }
}

// ---------------------------------------------------------------------------
// Flash attention (fp32, causal). One CTA per (q-block of 64, head, batch).
// 256 threads, 4x4 score microtile. Q and K stored transposed in smem so
// both score-GEMM operands are LDS.128. K^T buffer reused for P.
// ---------------------------------------------------------------------------
#define ATTN_SMEM_FLOATS (3 * 4096 + 2 * 1024 + 128)
#define ATTN_SMEM_BYTES  (ATTN_SMEM_FLOATS * 4)

__global__ __launch_bounds__(256) void flash_attn_kernel(
    const float* __restrict__ Q, const float* __restrict__ K,
    const float* __restrict__ V, float* __restrict__ O) {
  extern __shared__ float sm[];
  float* Qs   = sm;                // [64][64] transposed: Qs[k][r]
  float* KP   = Qs + 4096;         // K^T [k][c], later P [r][c]
  float* Vs   = KP + 4096;         // [j][dh]
  float* redA = Vs + 4096;         // [64][16] row-max partials
  float* redB = redA + 1024;       // [64][16] row-sum partials
  float* m_s  = redB + 1024;       // [64]
  float* l_s  = m_s + 64;          // [64]

  const int tid = threadIdx.x;
  const int tx = tid & 15;
  const int ty = tid >> 4;
  const int qb = blockIdx.x;   // 0..31
  const int h  = blockIdx.y;   // 0..15
  const int b  = blockIdx.z;   // 0..1
  const int q0 = qb << 6;

  const size_t base = ((size_t)b * S_LEN) * DMODEL + (size_t)h * DHEAD;
  const float* Qb = Q + base;
  const float* Kb = K + base;
  const float* Vb = V + base;

  // Load Q tile, pre-scaled by 1/sqrt(64)=0.125, stored transposed.
#pragma unroll
  for (int t = 0; t < 4; t++) {
    int idx = (tid << 2) + t;            // 0..1023
    int r = idx >> 4;                    // 0..63
    int c = (idx & 15) << 2;             // 0..60
    float4 q = *(const float4*)(Qb + (size_t)(q0 + r) * DMODEL + c);
    Qs[(c + 0) * 64 + r] = q.x * 0.125f;
    Qs[(c + 1) * 64 + r] = q.y * 0.125f;
    Qs[(c + 2) * 64 + r] = q.z * 0.125f;
    Qs[(c + 3) * 64 + r] = q.w * 0.125f;
  }
  if (tid < 64) { m_s[tid] = -1e30f; l_s[tid] = 0.0f; }

  float o[4][4] = {};
  __syncthreads();

  for (int jb = 0; jb <= qb; jb++) {
    const int j0 = jb << 6;

    // Load K (transposed) and V tiles
#pragma unroll
    for (int t = 0; t < 4; t++) {
      int idx = (tid << 2) + t;
      int r = idx >> 4;
      int c = (idx & 15) << 2;
      float4 kv = *(const float4*)(Kb + (size_t)(j0 + r) * DMODEL + c);
      KP[(c + 0) * 64 + r] = kv.x;
      KP[(c + 1) * 64 + r] = kv.y;
      KP[(c + 2) * 64 + r] = kv.z;
      KP[(c + 3) * 64 + r] = kv.w;
      float4 vv = *(const float4*)(Vb + (size_t)(j0 + r) * DMODEL + c);
      *(float4*)&Vs[r * 64 + c] = vv;
    }
    __syncthreads();

    // S = (Q*scale) @ K^T
    float s[4][4] = {};
#pragma unroll
    for (int k = 0; k < 64; k++) {
      float4 a = *(const float4*)&Qs[k * 64 + (ty << 2)];
      float4 bb = *(const float4*)&KP[k * 64 + (tx << 2)];
      float av[4] = {a.x, a.y, a.z, a.w};
      float bv[4] = {bb.x, bb.y, bb.z, bb.w};
#pragma unroll
      for (int i = 0; i < 4; i++)
#pragma unroll
        for (int j = 0; j < 4; j++)
          s[i][j] += av[i] * bv[j];
    }

    // Causal mask on the diagonal block
    if (jb == qb) {
#pragma unroll
      for (int i = 0; i < 4; i++)
#pragma unroll
        for (int j = 0; j < 4; j++)
          if (((tx << 2) + j) > ((ty << 2) + i)) s[i][j] = -1e30f;
    }

    // Row-max partials
#pragma unroll
    for (int i = 0; i < 4; i++) {
      float pm = fmaxf(fmaxf(s[i][0], s[i][1]), fmaxf(s[i][2], s[i][3]));
      redA[((ty << 2) + i) * 16 + tx] = pm;
    }
    __syncthreads();

    float scl[4], mnew[4];
#pragma unroll
    for (int i = 0; i < 4; i++) {
      int r = (ty << 2) + i;
      float mx = redA[r * 16];
#pragma unroll
      for (int t = 1; t < 16; t++) mx = fmaxf(mx, redA[r * 16 + t]);
      float mo = m_s[r];
      float mn = fmaxf(mo, mx);
      mnew[i] = mn;
      scl[i] = __expf(mo - mn);
      float rs = 0.0f;
#pragma unroll
      for (int j = 0; j < 4; j++) {
        s[i][j] = __expf(s[i][j] - mn);
        rs += s[i][j];
      }
      redB[r * 16 + tx] = rs;
      // P overwrites the K^T buffer (safe: all S reads done before last sync)
      *(float4*)&KP[r * 64 + (tx << 2)] =
          make_float4(s[i][0], s[i][1], s[i][2], s[i][3]);
    }
    __syncthreads();

#pragma unroll
    for (int i = 0; i < 4; i++) {
      int r = (ty << 2) + i;
      float rs = 0.0f;
#pragma unroll
      for (int t = 0; t < 16; t++) rs += redB[r * 16 + t];
      if (tx == 0) {
        l_s[r] = l_s[r] * scl[i] + rs;
        m_s[r] = mnew[i];
      }
#pragma unroll
      for (int j = 0; j < 4; j++) o[i][j] *= scl[i];
    }

    // O += P @ V
#pragma unroll
    for (int kk = 0; kk < 64; kk++) {
      float4 v = *(const float4*)&Vs[kk * 64 + (tx << 2)];
      float vv[4] = {v.x, v.y, v.z, v.w};
#pragma unroll
      for (int i = 0; i < 4; i++) {
        float p = KP[((ty << 2) + i) * 64 + kk];
#pragma unroll
        for (int j = 0; j < 4; j++) o[i][j] += p * vv[j];
      }
    }
    __syncthreads();   // protects KP/Vs overwrite next iter; publishes m_s/l_s
  }

  // Normalize and write context in [B,S,DMODEL] layout (heads interleaved)
#pragma unroll
  for (int i = 0; i < 4; i++) {
    int r = (ty << 2) + i;
    float inv = 1.0f / l_s[r];
    float4 v = make_float4(o[i][0] * inv, o[i][1] * inv,
                           o[i][2] * inv, o[i][3] * inv);
    *(float4*)(O + base + (size_t)(q0 + r) * DMODEL + (tx << 2)) = v;
  }
}

// ---------------------------------------------------------------------------
extern "C" void kernel_launch(void* const* d_in, const int* in_sizes, int n_in,
                              void* d_out, int out_size) {
  const float* x  = (const float*)d_in[0];
  const float* Wq = (const float*)d_in[1];
  const float* bq = (const float*)d_in[2];
  const float* Wk = (const float*)d_in[3];
  const float* bk = (const float*)d_in[4];
  const float* Wv = (const float*)d_in[5];
  const float* bv = (const float*)d_in[6];
  const float* Wo = (const float*)d_in[7];
  const float* bo = (const float*)d_in[8];
  float* out = (float*)d_out;

  float *Qp, *Kp, *Vp, *Cp;
  cudaGetSymbolAddress((void**)&Qp, g_Q);
  cudaGetSymbolAddress((void**)&Kp, g_K);
  cudaGetSymbolAddress((void**)&Vp, g_V);
  cudaGetSymbolAddress((void**)&Cp, g_CTX);

  cudaFuncSetAttribute(flash_attn_kernel,
                       cudaFuncAttributeMaxDynamicSharedMemorySize,
                       ATTN_SMEM_BYTES);

  dim3 gemm_grid(DMODEL / 64, M_TOT / 64);   // (16, 64)
  gemm_bias_kernel<<<gemm_grid, 256>>>(x, Wq, bq, Qp);
  gemm_bias_kernel<<<gemm_grid, 256>>>(x, Wk, bk, Kp);
  gemm_bias_kernel<<<gemm_grid, 256>>>(x, Wv, bv, Vp);

  dim3 attn_grid(S_LEN / 64, NHEAD, BATCH);  // (32, 16, 2)
  flash_attn_kernel<<<attn_grid, 256, ATTN_SMEM_BYTES>>>(Qp, Kp, Vp, Cp);

  gemm_bias_kernel<<<gemm_grid, 256>>>(Cp, Wo, bo, out);
}

// round 3
// speedup vs baseline: 1.5606x; 1.5606x over previous
#include <cuda_runtime.h>

#define S_LEN  2048
#define DMODEL 1024
#define BATCH  2
#define M_TOT  (BATCH * S_LEN)   // 4096
#define NHEAD  16
#define DHEAD  64
#define LOG2E  1.4426950408889634f

// Scratch (device globals — no allocation in kernel_launch)
__device__ float g_Q[M_TOT * DMODEL];
__device__ float g_K[M_TOT * DMODEL];
__device__ float g_V[M_TOT * DMODEL];
__device__ float g_CTX[M_TOT * DMODEL];

// ---------------------------------------------------------------------------
// GEMM: C[M_TOT, 1024] = A[M_TOT, 1024] @ B[1024, 1024] + bias
// BM=BN=64, BK=16, 256 threads, 4x4 register microtile per thread.
// ---------------------------------------------------------------------------
__global__ __launch_bounds__(256) void gemm_bias_kernel(
    const float* __restrict__ A, const float* __restrict__ B,
    const float* __restrict__ bias, float* __restrict__ C) {
  const int N = DMODEL, K = DMODEL;
  __shared__ float As[16][64];   // As[k][m]
  __shared__ float Bs[16][64];   // Bs[k][n]

  const int tid = threadIdx.x;
  const int tx = tid & 15;       // n group
  const int ty = tid >> 4;       // m group
  const int row0 = blockIdx.y << 6;
  const int col0 = blockIdx.x << 6;

  const int am = tid >> 2;
  const int ak = (tid & 3) << 2;
  const int bk = tid >> 4;
  const int bn = (tid & 15) << 2;

  const float* Ap = A + (size_t)(row0 + am) * K + ak;
  const float* Bp = B + (size_t)bk * N + col0 + bn;

  float acc[4][4] = {};

  for (int k0 = 0; k0 < K; k0 += 16) {
    float4 av = *(const float4*)(Ap + k0);
    float4 bv = *(const float4*)(Bp + (size_t)k0 * N);
    As[ak + 0][am] = av.x;
    As[ak + 1][am] = av.y;
    As[ak + 2][am] = av.z;
    As[ak + 3][am] = av.w;
    *(float4*)&Bs[bk][bn] = bv;
    __syncthreads();

#pragma unroll
    for (int k = 0; k < 16; k++) {
      float4 a = *(const float4*)&As[k][ty << 2];
      float4 b = *(const float4*)&Bs[k][tx << 2];
      float avr[4] = {a.x, a.y, a.z, a.w};
      float bvr[4] = {b.x, b.y, b.z, b.w};
#pragma unroll
      for (int i = 0; i < 4; i++)
#pragma unroll
        for (int j = 0; j < 4; j++)
          acc[i][j] += avr[i] * bvr[j];
    }
    __syncthreads();
  }

  float4 bb = *(const float4*)&bias[col0 + (tx << 2)];
  float bbr[4] = {bb.x, bb.y, bb.z, bb.w};
#pragma unroll
  for (int i = 0; i < 4; i++) {
    float4 v = make_float4(acc[i][0] + bbr[0], acc[i][1] + bbr[1],
                           acc[i][2] + bbr[2], acc[i][3] + bbr[3]);
    *(float4*)&C[(size_t)(row0 + (ty << 2) + i) * N + col0 + (tx << 2)] = v;
  }
}

// ---------------------------------------------------------------------------
// Flash attention v2 (fp32, causal).
// One CTA per (q-block 64, head, batch). 256 threads, 4x4 microtile.
// Softmax stats (m, l) live in registers; row reductions use shfl_xor
// butterflies over the 16 lanes that share a row group (same ty — all in one
// warp half). Zero smem traffic for reductions; 3 barriers per tile.
// exp() folded to exp2: Q pre-scaled by (1/sqrt(Dh)) * log2(e).
// ---------------------------------------------------------------------------
#define ATTN_SMEM_BYTES (4 * 4096 * 4)   // Qs + Ks + Vs + Ps = 64 KB

__global__ __launch_bounds__(256, 3) void flash_attn_kernel(
    const float* __restrict__ Q, const float* __restrict__ K,
    const float* __restrict__ V, float* __restrict__ O) {
  extern __shared__ float sm[];
  float* Qs = sm;             // [64][64] transposed: Qs[k][r]
  float* Ks = Qs + 4096;      // [64][64] transposed: Ks[k][c]
  float* Vs = Ks + 4096;      // [64][64] row-major: Vs[j][c]
  float* Ps = Vs + 4096;      // [64][64] row-major: Ps[r][c]

  const int tid = threadIdx.x;
  const int tx = tid & 15;    // col group (4 cols)
  const int ty = tid >> 4;    // row group (4 rows)
  const int qb = blockIdx.x;  // 0..31
  const int h  = blockIdx.y;
  const int b  = blockIdx.z;
  const int q0 = qb << 6;

  const size_t base = ((size_t)b * S_LEN) * DMODEL + (size_t)h * DHEAD;
  const float* Qb = Q + base;
  const float* Kb = K + base;
  const float* Vb = V + base;

  // Load Q tile, pre-scaled by 0.125 * log2(e), stored transposed.
  const float qscale = 0.125f * LOG2E;
#pragma unroll
  for (int t = 0; t < 4; t++) {
    int idx = (tid << 2) + t;            // 0..1023
    int r = idx >> 4;
    int c = (idx & 15) << 2;
    float4 q = *(const float4*)(Qb + (size_t)(q0 + r) * DMODEL + c);
    Qs[(c + 0) * 64 + r] = q.x * qscale;
    Qs[(c + 1) * 64 + r] = q.y * qscale;
    Qs[(c + 2) * 64 + r] = q.z * qscale;
    Qs[(c + 3) * 64 + r] = q.w * qscale;
  }

  float m[4], l[4];
  float o[4][4] = {};
#pragma unroll
  for (int i = 0; i < 4; i++) { m[i] = -1e30f; l[i] = 0.0f; }

  for (int jb = 0; jb <= qb; jb++) {
    const int j0 = jb << 6;

    __syncthreads();   // prior PV done (and Q stores visible on first iter)

    // Load K (transposed) and V tiles
#pragma unroll
    for (int t = 0; t < 4; t++) {
      int idx = (tid << 2) + t;
      int r = idx >> 4;
      int c = (idx & 15) << 2;
      float4 kv = *(const float4*)(Kb + (size_t)(j0 + r) * DMODEL + c);
      Ks[(c + 0) * 64 + r] = kv.x;
      Ks[(c + 1) * 64 + r] = kv.y;
      Ks[(c + 2) * 64 + r] = kv.z;
      Ks[(c + 3) * 64 + r] = kv.w;
      float4 vv = *(const float4*)(Vb + (size_t)(j0 + r) * DMODEL + c);
      *(float4*)&Vs[r * 64 + c] = vv;
    }
    __syncthreads();

    // S = (Q * qscale) @ K^T   (log2-domain scores)
    float s[4][4] = {};
#pragma unroll
    for (int k = 0; k < 64; k++) {
      float4 a  = *(const float4*)&Qs[k * 64 + (ty << 2)];
      float4 bb = *(const float4*)&Ks[k * 64 + (tx << 2)];
      float av[4] = {a.x, a.y, a.z, a.w};
      float bv[4] = {bb.x, bb.y, bb.z, bb.w};
#pragma unroll
      for (int i = 0; i < 4; i++)
#pragma unroll
        for (int j = 0; j < 4; j++)
          s[i][j] += av[i] * bv[j];
    }

    // Causal mask on the diagonal block
    if (jb == qb) {
#pragma unroll
      for (int i = 0; i < 4; i++)
#pragma unroll
        for (int j = 0; j < 4; j++)
          if (((tx << 2) + j) > ((ty << 2) + i)) s[i][j] = -1e30f;
    }

    // Online softmax: register stats + shuffle reductions (16-lane groups)
#pragma unroll
    for (int i = 0; i < 4; i++) {
      float mx = fmaxf(fmaxf(s[i][0], s[i][1]), fmaxf(s[i][2], s[i][3]));
#pragma unroll
      for (int w = 1; w < 16; w <<= 1)
        mx = fmaxf(mx, __shfl_xor_sync(0xffffffffu, mx, w));
      float mn  = fmaxf(m[i], mx);
      float scl = exp2f(m[i] - mn);
      m[i] = mn;
      float rs = 0.0f;
#pragma unroll
      for (int j = 0; j < 4; j++) {
        s[i][j] = exp2f(s[i][j] - mn);
        rs += s[i][j];
      }
#pragma unroll
      for (int w = 1; w < 16; w <<= 1)
        rs += __shfl_xor_sync(0xffffffffu, rs, w);
      l[i] = l[i] * scl + rs;
#pragma unroll
      for (int j = 0; j < 4; j++) o[i][j] *= scl;
      *(float4*)&Ps[((ty << 2) + i) * 64 + (tx << 2)] =
          make_float4(s[i][0], s[i][1], s[i][2], s[i][3]);
    }
    __syncthreads();   // P visible

    // O += P @ V
#pragma unroll
    for (int kk = 0; kk < 64; kk++) {
      float4 v = *(const float4*)&Vs[kk * 64 + (tx << 2)];
      float vv[4] = {v.x, v.y, v.z, v.w};
#pragma unroll
      for (int i = 0; i < 4; i++) {
        float p = Ps[((ty << 2) + i) * 64 + kk];
#pragma unroll
        for (int j = 0; j < 4; j++) o[i][j] += p * vv[j];
      }
    }
  }

  // Normalize and write context in [B,S,DMODEL] layout
#pragma unroll
  for (int i = 0; i < 4; i++) {
    int r = (ty << 2) + i;
    float inv = 1.0f / l[i];
    float4 v = make_float4(o[i][0] * inv, o[i][1] * inv,
                           o[i][2] * inv, o[i][3] * inv);
    *(float4*)(O + base + (size_t)(q0 + r) * DMODEL + (tx << 2)) = v;
  }
}

// ---------------------------------------------------------------------------
extern "C" void kernel_launch(void* const* d_in, const int* in_sizes, int n_in,
                              void* d_out, int out_size) {
  const float* x  = (const float*)d_in[0];
  const float* Wq = (const float*)d_in[1];
  const float* bq = (const float*)d_in[2];
  const float* Wk = (const float*)d_in[3];
  const float* bk = (const float*)d_in[4];
  const float* Wv = (const float*)d_in[5];
  const float* bv = (const float*)d_in[6];
  const float* Wo = (const float*)d_in[7];
  const float* bo = (const float*)d_in[8];
  float* out = (float*)d_out;

  float *Qp, *Kp, *Vp, *Cp;
  cudaGetSymbolAddress((void**)&Qp, g_Q);
  cudaGetSymbolAddress((void**)&Kp, g_K);
  cudaGetSymbolAddress((void**)&Vp, g_V);
  cudaGetSymbolAddress((void**)&Cp, g_CTX);

  cudaFuncSetAttribute(flash_attn_kernel,
                       cudaFuncAttributeMaxDynamicSharedMemorySize,
                       ATTN_SMEM_BYTES);

  dim3 gemm_grid(DMODEL / 64, M_TOT / 64);   // (16, 64)
  gemm_bias_kernel<<<gemm_grid, 256>>>(x, Wq, bq, Qp);
  gemm_bias_kernel<<<gemm_grid, 256>>>(x, Wk, bk, Kp);
  gemm_bias_kernel<<<gemm_grid, 256>>>(x, Wv, bv, Vp);

  dim3 attn_grid(S_LEN / 64, NHEAD, BATCH);  // (32, 16, 2)
  flash_attn_kernel<<<attn_grid, 256, ATTN_SMEM_BYTES>>>(Qp, Kp, Vp, Cp);

  gemm_bias_kernel<<<gemm_grid, 256>>>(Cp, Wo, bo, out);
}

// round 7
// speedup vs baseline: 2.8171x; 1.8052x over previous
#include <cuda_runtime.h>
#include <cstdint>

#define S_LEN  2048
#define DMODEL 1024
#define BATCH  2
#define M_TOT  (BATCH * S_LEN)   // 4096
#define NHEAD  16
#define DHEAD  64
#define LOG2E  1.4426950408889634f

// Scratch (device globals — no allocation in kernel_launch)
__device__ float g_Q[M_TOT * DMODEL];
__device__ float g_K[M_TOT * DMODEL];
__device__ float g_V[M_TOT * DMODEL];
__device__ float g_CTX[M_TOT * DMODEL];
__device__ float g_Ar[M_TOT * DMODEL];    // tf32-rounded activations
__device__ float g_Wr[DMODEL * DMODEL];   // tf32-rounded weights (reused)

// ---------------------------------------------------------------------------
__device__ __forceinline__ float to_tf32(float x) {
  float r;
  asm("cvt.rna.tf32.f32 %0, %1;" : "=f"(r) : "f"(x));
  return r;
}
__device__ __forceinline__ uint32_t smem_u32(const void* p) {
  uint32_t a;
  asm("{ .reg .u64 t; cvta.to.shared.u64 t, %1; cvt.u32.u64 %0, t; }"
      : "=r"(a) : "l"(p));
  return a;
}
__device__ __forceinline__ void cp16(uint32_t s, const void* g) {
  asm volatile("cp.async.cg.shared.global [%0], [%1], 16;"
               :: "r"(s), "l"(g));
}
__device__ __forceinline__ void mma_tf32(float* d, const float* a,
                                         const float* b) {
  asm volatile(
      "mma.sync.aligned.m16n8k8.row.col.f32.tf32.tf32.f32 "
      "{%0,%1,%2,%3}, {%4,%5,%6,%7}, {%8,%9}, {%0,%1,%2,%3};"
      : "+f"(d[0]), "+f"(d[1]), "+f"(d[2]), "+f"(d[3])
      : "r"(__float_as_uint(a[0])), "r"(__float_as_uint(a[1])),
        "r"(__float_as_uint(a[2])), "r"(__float_as_uint(a[3])),
        "r"(__float_as_uint(b[0])), "r"(__float_as_uint(b[1])));
}

// ---------------------------------------------------------------------------
// Elementwise fp32 -> tf32-rounded fp32 (RN), vectorized by 4
// ---------------------------------------------------------------------------
__global__ __launch_bounds__(256) void cvt_tf32_kernel(
    const float* __restrict__ in, float* __restrict__ out, int n4) {
  int i = blockIdx.x * 256 + threadIdx.x;
  if (i >= n4) return;
  float4 v = ((const float4*)in)[i];
  v.x = to_tf32(v.x);
  v.y = to_tf32(v.y);
  v.z = to_tf32(v.z);
  v.w = to_tf32(v.w);
  ((float4*)out)[i] = v;
}

// ---------------------------------------------------------------------------
// tf32 tensor-core GEMM: C[4096,1024] = A[4096,1024] @ B[1024,1024] + bias
// Inputs already tf32-rounded. 128x128 CTA tile, BK=32, cp.async double
// buffer. 8 warps: warp_m = wid&1 (64 rows), warp_n = wid>>1 (32 cols).
// Padded smem strides (A:36, B:132 floats) -> conflict-free fragment loads.
// ---------------------------------------------------------------------------
#define AS_STRIDE 36
#define BS_STRIDE 132
#define AS_FLOATS (128 * AS_STRIDE)          // 4608 per stage
#define BS_FLOATS (32 * BS_STRIDE)           // 4224 per stage
#define GT_SMEM_BYTES ((2 * AS_FLOATS + 2 * BS_FLOATS) * 4)  // 70656

__global__ __launch_bounds__(256) void gemm_tf32_kernel(
    const float* __restrict__ A, const float* __restrict__ B,
    const float* __restrict__ bias, float* __restrict__ C) {
  extern __shared__ float sm[];
  const uint32_t sbase = smem_u32(sm);

  const int tid = threadIdx.x;
  const int wid = tid >> 5;
  const int lane = tid & 31;
  const int g = lane >> 2;    // group 0..7
  const int t = lane & 3;     // thread-in-group 0..3
  const int warp_m = wid & 1;       // 0..1 -> 64-row slab
  const int warp_n = wid >> 1;      // 0..3 -> 32-col slab
  const int row0 = blockIdx.y << 7;
  const int col0 = blockIdx.x << 7;

  float acc[4][4][4] = {};   // [m-frag][n-frag][reg]

#define ISSUE(kt)                                                              \
  do {                                                                         \
    int _buf = (kt) & 1;                                                       \
    uint32_t _sA = sbase + _buf * (AS_FLOATS * 4);                             \
    uint32_t _sB = sbase + (2 * AS_FLOATS + _buf * BS_FLOATS) * 4;             \
    _Pragma("unroll") for (int i = 0; i < 4; i++) {                            \
      int idx = tid + 256 * i;                                                 \
      int r = idx >> 3, c4 = idx & 7;                                          \
      cp16(_sA + r * (AS_STRIDE * 4) + c4 * 16,                                \
           A + (size_t)(row0 + r) * DMODEL + (kt) * 32 + c4 * 4);              \
    }                                                                          \
    _Pragma("unroll") for (int i = 0; i < 4; i++) {                            \
      int idx = tid + 256 * i;                                                 \
      int r = idx >> 5, c4 = idx & 31;                                         \
      cp16(_sB + r * (BS_STRIDE * 4) + c4 * 16,                                \
           B + (size_t)((kt) * 32 + r) * DMODEL + col0 + c4 * 4);              \
    }                                                                          \
    asm volatile("cp.async.commit_group;" ::: "memory");                       \
  } while (0)

  ISSUE(0);

  const int NT = DMODEL / 32;   // 32
  for (int kt = 0; kt < NT; kt++) {
    if (kt + 1 < NT) {
      ISSUE(kt + 1);
      asm volatile("cp.async.wait_group 1;" ::: "memory");
    } else {
      asm volatile("cp.async.wait_group 0;" ::: "memory");
    }
    __syncthreads();

    const float* as_ = sm + (kt & 1) * AS_FLOATS;
    const float* bs_ = sm + 2 * AS_FLOATS + (kt & 1) * BS_FLOATS;

#pragma unroll
    for (int ks = 0; ks < 4; ks++) {
      float a[4][4], b[4][2];
#pragma unroll
      for (int mf = 0; mf < 4; mf++) {
        int rw = warp_m * 64 + mf * 16 + g;
        int c = ks * 8 + t;
        a[mf][0] = as_[rw * AS_STRIDE + c];
        a[mf][1] = as_[(rw + 8) * AS_STRIDE + c];
        a[mf][2] = as_[rw * AS_STRIDE + c + 4];
        a[mf][3] = as_[(rw + 8) * AS_STRIDE + c + 4];
      }
#pragma unroll
      for (int nf = 0; nf < 4; nf++) {
        int cn = warp_n * 32 + nf * 8 + g;
        int rk = ks * 8 + t;
        b[nf][0] = bs_[rk * BS_STRIDE + cn];
        b[nf][1] = bs_[(rk + 4) * BS_STRIDE + cn];
      }
#pragma unroll
      for (int mf = 0; mf < 4; mf++)
#pragma unroll
        for (int nf = 0; nf < 4; nf++)
          mma_tf32(acc[mf][nf], a[mf], b[nf]);
    }
    __syncthreads();
  }

  // Epilogue: + bias, write fp32
#pragma unroll
  for (int mf = 0; mf < 4; mf++) {
#pragma unroll
    for (int nf = 0; nf < 4; nf++) {
      int col = col0 + warp_n * 32 + nf * 8 + t * 2;
      float2 bb = *(const float2*)(bias + col);
      int r0 = row0 + warp_m * 64 + mf * 16 + g;
      float2 v0 = make_float2(acc[mf][nf][0] + bb.x, acc[mf][nf][1] + bb.y);
      float2 v1 = make_float2(acc[mf][nf][2] + bb.x, acc[mf][nf][3] + bb.y);
      *(float2*)(C + (size_t)r0 * DMODEL + col) = v0;
      *(float2*)(C + (size_t)(r0 + 8) * DMODEL + col) = v1;
    }
  }
#undef ISSUE
}

// ---------------------------------------------------------------------------
// Flash attention (fp32, causal) — unchanged from R3
// ---------------------------------------------------------------------------
#define ATTN_SMEM_BYTES (4 * 4096 * 4)

__global__ __launch_bounds__(256, 3) void flash_attn_kernel(
    const float* __restrict__ Q, const float* __restrict__ K,
    const float* __restrict__ V, float* __restrict__ O) {
  extern __shared__ float sm[];
  float* Qs = sm;
  float* Ks = Qs + 4096;
  float* Vs = Ks + 4096;
  float* Ps = Vs + 4096;

  const int tid = threadIdx.x;
  const int tx = tid & 15;
  const int ty = tid >> 4;
  const int qb = blockIdx.x;
  const int h  = blockIdx.y;
  const int b  = blockIdx.z;
  const int q0 = qb << 6;

  const size_t base = ((size_t)b * S_LEN) * DMODEL + (size_t)h * DHEAD;
  const float* Qb = Q + base;
  const float* Kb = K + base;
  const float* Vb = V + base;

  const float qscale = 0.125f * LOG2E;
#pragma unroll
  for (int t = 0; t < 4; t++) {
    int idx = (tid << 2) + t;
    int r = idx >> 4;
    int c = (idx & 15) << 2;
    float4 q = *(const float4*)(Qb + (size_t)(q0 + r) * DMODEL + c);
    Qs[(c + 0) * 64 + r] = q.x * qscale;
    Qs[(c + 1) * 64 + r] = q.y * qscale;
    Qs[(c + 2) * 64 + r] = q.z * qscale;
    Qs[(c + 3) * 64 + r] = q.w * qscale;
  }

  float m[4], l[4];
  float o[4][4] = {};
#pragma unroll
  for (int i = 0; i < 4; i++) { m[i] = -1e30f; l[i] = 0.0f; }

  for (int jb = 0; jb <= qb; jb++) {
    const int j0 = jb << 6;
    __syncthreads();
#pragma unroll
    for (int t = 0; t < 4; t++) {
      int idx = (tid << 2) + t;
      int r = idx >> 4;
      int c = (idx & 15) << 2;
      float4 kv = *(const float4*)(Kb + (size_t)(j0 + r) * DMODEL + c);
      Ks[(c + 0) * 64 + r] = kv.x;
      Ks[(c + 1) * 64 + r] = kv.y;
      Ks[(c + 2) * 64 + r] = kv.z;
      Ks[(c + 3) * 64 + r] = kv.w;
      float4 vv = *(const float4*)(Vb + (size_t)(j0 + r) * DMODEL + c);
      *(float4*)&Vs[r * 64 + c] = vv;
    }
    __syncthreads();

    float s[4][4] = {};
#pragma unroll
    for (int k = 0; k < 64; k++) {
      float4 a  = *(const float4*)&Qs[k * 64 + (ty << 2)];
      float4 bb = *(const float4*)&Ks[k * 64 + (tx << 2)];
      float av[4] = {a.x, a.y, a.z, a.w};
      float bv[4] = {bb.x, bb.y, bb.z, bb.w};
#pragma unroll
      for (int i = 0; i < 4; i++)
#pragma unroll
        for (int j = 0; j < 4; j++)
          s[i][j] += av[i] * bv[j];
    }

    if (jb == qb) {
#pragma unroll
      for (int i = 0; i < 4; i++)
#pragma unroll
        for (int j = 0; j < 4; j++)
          if (((tx << 2) + j) > ((ty << 2) + i)) s[i][j] = -1e30f;
    }

#pragma unroll
    for (int i = 0; i < 4; i++) {
      float mx = fmaxf(fmaxf(s[i][0], s[i][1]), fmaxf(s[i][2], s[i][3]));
#pragma unroll
      for (int w = 1; w < 16; w <<= 1)
        mx = fmaxf(mx, __shfl_xor_sync(0xffffffffu, mx, w));
      float mn  = fmaxf(m[i], mx);
      float scl = exp2f(m[i] - mn);
      m[i] = mn;
      float rs = 0.0f;
#pragma unroll
      for (int j = 0; j < 4; j++) {
        s[i][j] = exp2f(s[i][j] - mn);
        rs += s[i][j];
      }
#pragma unroll
      for (int w = 1; w < 16; w <<= 1)
        rs += __shfl_xor_sync(0xffffffffu, rs, w);
      l[i] = l[i] * scl + rs;
#pragma unroll
      for (int j = 0; j < 4; j++) o[i][j] *= scl;
      *(float4*)&Ps[((ty << 2) + i) * 64 + (tx << 2)] =
          make_float4(s[i][0], s[i][1], s[i][2], s[i][3]);
    }
    __syncthreads();

#pragma unroll
    for (int kk = 0; kk < 64; kk++) {
      float4 v = *(const float4*)&Vs[kk * 64 + (tx << 2)];
      float vv[4] = {v.x, v.y, v.z, v.w};
#pragma unroll
      for (int i = 0; i < 4; i++) {
        float p = Ps[((ty << 2) + i) * 64 + kk];
#pragma unroll
        for (int j = 0; j < 4; j++) o[i][j] += p * vv[j];
      }
    }
  }

#pragma unroll
  for (int i = 0; i < 4; i++) {
    int r = (ty << 2) + i;
    float inv = 1.0f / l[i];
    float4 v = make_float4(o[i][0] * inv, o[i][1] * inv,
                           o[i][2] * inv, o[i][3] * inv);
    *(float4*)(O + base + (size_t)(q0 + r) * DMODEL + (tx << 2)) = v;
  }
}

// ---------------------------------------------------------------------------
extern "C" void kernel_launch(void* const* d_in, const int* in_sizes, int n_in,
                              void* d_out, int out_size) {
  const float* x  = (const float*)d_in[0];
  const float* Wq = (const float*)d_in[1];
  const float* bq = (const float*)d_in[2];
  const float* Wk = (const float*)d_in[3];
  const float* bk = (const float*)d_in[4];
  const float* Wv = (const float*)d_in[5];
  const float* bv = (const float*)d_in[6];
  const float* Wo = (const float*)d_in[7];
  const float* bo = (const float*)d_in[8];
  float* out = (float*)d_out;

  float *Qp, *Kp, *Vp, *Cp, *Ar, *Wr;
  cudaGetSymbolAddress((void**)&Qp, g_Q);
  cudaGetSymbolAddress((void**)&Kp, g_K);
  cudaGetSymbolAddress((void**)&Vp, g_V);
  cudaGetSymbolAddress((void**)&Cp, g_CTX);
  cudaGetSymbolAddress((void**)&Ar, g_Ar);
  cudaGetSymbolAddress((void**)&Wr, g_Wr);

  cudaFuncSetAttribute(flash_attn_kernel,
                       cudaFuncAttributeMaxDynamicSharedMemorySize,
                       ATTN_SMEM_BYTES);
  cudaFuncSetAttribute(gemm_tf32_kernel,
                       cudaFuncAttributeMaxDynamicSharedMemorySize,
                       GT_SMEM_BYTES);

  const int nA4 = M_TOT * DMODEL / 4;     // 1M
  const int nW4 = DMODEL * DMODEL / 4;    // 256K
  dim3 ggrid(DMODEL / 128, M_TOT / 128);  // (8, 32)

  cvt_tf32_kernel<<<nA4 / 256, 256>>>(x, Ar, nA4);

  cvt_tf32_kernel<<<nW4 / 256, 256>>>(Wq, Wr, nW4);
  gemm_tf32_kernel<<<ggrid, 256, GT_SMEM_BYTES>>>(Ar, Wr, bq, Qp);
  cvt_tf32_kernel<<<nW4 / 256, 256>>>(Wk, Wr, nW4);
  gemm_tf32_kernel<<<ggrid, 256, GT_SMEM_BYTES>>>(Ar, Wr, bk, Kp);
  cvt_tf32_kernel<<<nW4 / 256, 256>>>(Wv, Wr, nW4);
  gemm_tf32_kernel<<<ggrid, 256, GT_SMEM_BYTES>>>(Ar, Wr, bv, Vp);

  dim3 attn_grid(S_LEN / 64, NHEAD, BATCH);
  flash_attn_kernel<<<attn_grid, 256, ATTN_SMEM_BYTES>>>(Qp, Kp, Vp, Cp);

  cvt_tf32_kernel<<<nA4 / 256, 256>>>(Cp, Ar, nA4);
  cvt_tf32_kernel<<<nW4 / 256, 256>>>(Wo, Wr, nW4);
  gemm_tf32_kernel<<<ggrid, 256, GT_SMEM_BYTES>>>(Ar, Wr, bo, out);
}

// round 10
// speedup vs baseline: 4.9970x; 1.7738x over previous
#include <cuda_runtime.h>
#include <cstdint>

#define S_LEN  2048
#define DMODEL 1024
#define BATCH  2
#define M_TOT  (BATCH * S_LEN)   // 4096
#define NHEAD  16
#define DHEAD  64
#define LOG2E  1.4426950408889634f

// Scratch (device globals — no allocation in kernel_launch)
__device__ float g_Q[M_TOT * DMODEL];
__device__ float g_K[M_TOT * DMODEL];
__device__ float g_V[M_TOT * DMODEL];
__device__ float g_CTX[M_TOT * DMODEL];
__device__ float g_Ar[M_TOT * DMODEL];    // tf32-rounded activations
__device__ float g_Wr[DMODEL * DMODEL];   // tf32-rounded weights (reused)

// ---------------------------------------------------------------------------
__device__ __forceinline__ float to_tf32(float x) {
  float r;
  asm("cvt.rna.tf32.f32 %0, %1;" : "=f"(r) : "f"(x));
  return r;
}
__device__ __forceinline__ uint32_t smem_u32(const void* p) {
  uint32_t a;
  asm("{ .reg .u64 t; cvta.to.shared.u64 t, %1; cvt.u32.u64 %0, t; }"
      : "=r"(a) : "l"(p));
  return a;
}
__device__ __forceinline__ void cp16(uint32_t s, const void* g) {
  asm volatile("cp.async.cg.shared.global [%0], [%1], 16;"
               :: "r"(s), "l"(g));
}
__device__ __forceinline__ void mma_tf32(float* d, const float* a,
                                         const float* b) {
  asm volatile(
      "mma.sync.aligned.m16n8k8.row.col.f32.tf32.tf32.f32 "
      "{%0,%1,%2,%3}, {%4,%5,%6,%7}, {%8,%9}, {%0,%1,%2,%3};"
      : "+f"(d[0]), "+f"(d[1]), "+f"(d[2]), "+f"(d[3])
      : "r"(__float_as_uint(a[0])), "r"(__float_as_uint(a[1])),
        "r"(__float_as_uint(a[2])), "r"(__float_as_uint(a[3])),
        "r"(__float_as_uint(b[0])), "r"(__float_as_uint(b[1])));
}

// ---------------------------------------------------------------------------
// Elementwise fp32 -> tf32-rounded fp32 (RN), vectorized by 4
// ---------------------------------------------------------------------------
__global__ __launch_bounds__(256) void cvt_tf32_kernel(
    const float* __restrict__ in, float* __restrict__ out, int n4) {
  int i = blockIdx.x * 256 + threadIdx.x;
  if (i >= n4) return;
  float4 v = ((const float4*)in)[i];
  v.x = to_tf32(v.x);
  v.y = to_tf32(v.y);
  v.z = to_tf32(v.z);
  v.w = to_tf32(v.w);
  ((float4*)out)[i] = v;
}

// ---------------------------------------------------------------------------
// tf32 tensor-core GEMM (unchanged from R7, passing at ~62us/GEMM)
// ---------------------------------------------------------------------------
#define AS_STRIDE 36
#define BS_STRIDE 132
#define AS_FLOATS (128 * AS_STRIDE)
#define BS_FLOATS (32 * BS_STRIDE)
#define GT_SMEM_BYTES ((2 * AS_FLOATS + 2 * BS_FLOATS) * 4)

__global__ __launch_bounds__(256) void gemm_tf32_kernel(
    const float* __restrict__ A, const float* __restrict__ B,
    const float* __restrict__ bias, float* __restrict__ C) {
  extern __shared__ float sm[];
  const uint32_t sbase = smem_u32(sm);

  const int tid = threadIdx.x;
  const int wid = tid >> 5;
  const int lane = tid & 31;
  const int g = lane >> 2;
  const int t = lane & 3;
  const int warp_m = wid & 1;
  const int warp_n = wid >> 1;
  const int row0 = blockIdx.y << 7;
  const int col0 = blockIdx.x << 7;

  float acc[4][4][4] = {};

#define ISSUE(kt)                                                              \
  do {                                                                         \
    int _buf = (kt) & 1;                                                       \
    uint32_t _sA = sbase + _buf * (AS_FLOATS * 4);                             \
    uint32_t _sB = sbase + (2 * AS_FLOATS + _buf * BS_FLOATS) * 4;             \
    _Pragma("unroll") for (int i = 0; i < 4; i++) {                            \
      int idx = tid + 256 * i;                                                 \
      int r = idx >> 3, c4 = idx & 7;                                          \
      cp16(_sA + r * (AS_STRIDE * 4) + c4 * 16,                                \
           A + (size_t)(row0 + r) * DMODEL + (kt) * 32 + c4 * 4);              \
    }                                                                          \
    _Pragma("unroll") for (int i = 0; i < 4; i++) {                            \
      int idx = tid + 256 * i;                                                 \
      int r = idx >> 5, c4 = idx & 31;                                         \
      cp16(_sB + r * (BS_STRIDE * 4) + c4 * 16,                                \
           B + (size_t)((kt) * 32 + r) * DMODEL + col0 + c4 * 4);              \
    }                                                                          \
    asm volatile("cp.async.commit_group;" ::: "memory");                       \
  } while (0)

  ISSUE(0);

  const int NT = DMODEL / 32;
  for (int kt = 0; kt < NT; kt++) {
    if (kt + 1 < NT) {
      ISSUE(kt + 1);
      asm volatile("cp.async.wait_group 1;" ::: "memory");
    } else {
      asm volatile("cp.async.wait_group 0;" ::: "memory");
    }
    __syncthreads();

    const float* as_ = sm + (kt & 1) * AS_FLOATS;
    const float* bs_ = sm + 2 * AS_FLOATS + (kt & 1) * BS_FLOATS;

#pragma unroll
    for (int ks = 0; ks < 4; ks++) {
      float a[4][4], b[4][2];
#pragma unroll
      for (int mf = 0; mf < 4; mf++) {
        int rw = warp_m * 64 + mf * 16 + g;
        int c = ks * 8 + t;
        a[mf][0] = as_[rw * AS_STRIDE + c];
        a[mf][1] = as_[(rw + 8) * AS_STRIDE + c];
        a[mf][2] = as_[rw * AS_STRIDE + c + 4];
        a[mf][3] = as_[(rw + 8) * AS_STRIDE + c + 4];
      }
#pragma unroll
      for (int nf = 0; nf < 4; nf++) {
        int cn = warp_n * 32 + nf * 8 + g;
        int rk = ks * 8 + t;
        b[nf][0] = bs_[rk * BS_STRIDE + cn];
        b[nf][1] = bs_[(rk + 4) * BS_STRIDE + cn];
      }
#pragma unroll
      for (int mf = 0; mf < 4; mf++)
#pragma unroll
        for (int nf = 0; nf < 4; nf++)
          mma_tf32(acc[mf][nf], a[mf], b[nf]);
    }
    __syncthreads();
  }

#pragma unroll
  for (int mf = 0; mf < 4; mf++) {
#pragma unroll
    for (int nf = 0; nf < 4; nf++) {
      int col = col0 + warp_n * 32 + nf * 8 + t * 2;
      float2 bb = *(const float2*)(bias + col);
      int r0 = row0 + warp_m * 64 + mf * 16 + g;
      float2 v0 = make_float2(acc[mf][nf][0] + bb.x, acc[mf][nf][1] + bb.y);
      float2 v1 = make_float2(acc[mf][nf][2] + bb.x, acc[mf][nf][3] + bb.y);
      *(float2*)(C + (size_t)r0 * DMODEL + col) = v0;
      *(float2*)(C + (size_t)(r0 + 8) * DMODEL + col) = v1;
    }
  }
#undef ISSUE
}

// ---------------------------------------------------------------------------
// Tensor-core flash attention (tf32 mma.sync, causal).
// CTA: 128 q-rows x (kv tiles of 64). 8 warps x 16 rows. m16n8k8 fragments.
// All smem row-major with stride 72 (conflict-free fragment loads).
// Softmax stats in registers, quad shfl reductions. P round-trips through
// smem (tf32-rounded) to re-fragment as the A operand of PV.
// ---------------------------------------------------------------------------
#define BQ  128
#define BKV 64
#define STR 72
#define AT_QS 0
#define AT_KS (BQ * STR)                    // 9216
#define AT_VS (AT_KS + BKV * STR)           // 13824
#define AT_PS (AT_VS + BKV * STR)           // 18432
#define ATTN_SMEM_FLOATS (AT_PS + BQ * STR) // 27648
#define ATTN_SMEM_BYTES  (ATTN_SMEM_FLOATS * 4)  // 110592

__global__ __launch_bounds__(256) void flash_attn_tc_kernel(
    const float* __restrict__ Q, const float* __restrict__ K,
    const float* __restrict__ V, float* __restrict__ O) {
  extern __shared__ float sm[];
  float* Qs = sm + AT_QS;   // [128][72]  q rows (scaled, tf32)
  float* Ks = sm + AT_KS;   // [64][72]   kv rows (tf32)
  float* Vs = sm + AT_VS;   // [64][72]   kv rows (tf32)
  float* Ps = sm + AT_PS;   // [128][72]  probabilities (tf32)

  const int tid = threadIdx.x;
  const int wid = tid >> 5;
  const int lane = tid & 31;
  const int g = lane >> 2;    // 0..7
  const int t = lane & 3;     // 0..3
  const int qb = (gridDim.x - 1) - blockIdx.x;   // heavy CTAs first
  const int h  = blockIdx.y;
  const int b  = blockIdx.z;
  const int q0 = qb * BQ;
  const int wrow = wid * 16;  // warp's 16-row block within the q tile

  const size_t base = ((size_t)b * S_LEN) * DMODEL + (size_t)h * DHEAD;
  const float* Qb = Q + base;
  const float* Kb = K + base;
  const float* Vb = V + base;

  // Load Q tile (128x64), scale by 0.125*log2(e), round to tf32.
  const float qscale = 0.125f * LOG2E;
#pragma unroll
  for (int i = 0; i < 8; i++) {
    int idx = tid + 256 * i;        // 0..2047 float4s
    int r = idx >> 4;               // 0..127
    int c = (idx & 15) << 2;        // 0..60
    float4 q = *(const float4*)(Qb + (size_t)(q0 + r) * DMODEL + c);
    q.x = to_tf32(q.x * qscale);
    q.y = to_tf32(q.y * qscale);
    q.z = to_tf32(q.z * qscale);
    q.w = to_tf32(q.w * qscale);
    *(float4*)&Qs[r * STR + c] = q;
  }

  float m0 = -1e30f, m1 = -1e30f, l0 = 0.0f, l1 = 0.0f;
  float o[8][4] = {};

  const int ntiles = 2 * qb + 2;
  for (int jt = 0; jt < ntiles; jt++) {
    const int j0 = jt * BKV;
    __syncthreads();   // Q visible (first iter); prior PV reads done

    // Load K and V tiles (64x64 each), tf32-rounded, row-major stride 72.
#pragma unroll
    for (int i = 0; i < 4; i++) {
      int idx = tid + 256 * i;
      int r = idx >> 4;
      int c = (idx & 15) << 2;
      float4 kv = *(const float4*)(Kb + (size_t)(j0 + r) * DMODEL + c);
      kv.x = to_tf32(kv.x); kv.y = to_tf32(kv.y);
      kv.z = to_tf32(kv.z); kv.w = to_tf32(kv.w);
      *(float4*)&Ks[r * STR + c] = kv;
      float4 vv = *(const float4*)(Vb + (size_t)(j0 + r) * DMODEL + c);
      vv.x = to_tf32(vv.x); vv.y = to_tf32(vv.y);
      vv.z = to_tf32(vv.z); vv.w = to_tf32(vv.w);
      *(float4*)&Vs[r * STR + c] = vv;
    }
    __syncthreads();

    // S[16,64] = Q_warp @ K^T : 8 k-steps x 8 n-frags
    float s[8][4] = {};
#pragma unroll
    for (int ks = 0; ks < 8; ks++) {
      float a[4];
      a[0] = Qs[(wrow + g) * STR + ks * 8 + t];
      a[1] = Qs[(wrow + g + 8) * STR + ks * 8 + t];
      a[2] = Qs[(wrow + g) * STR + ks * 8 + t + 4];
      a[3] = Qs[(wrow + g + 8) * STR + ks * 8 + t + 4];
#pragma unroll
      for (int nf = 0; nf < 8; nf++) {
        float bfr[2];
        bfr[0] = Ks[(nf * 8 + g) * STR + ks * 8 + t];      // K^T[k][n]
        bfr[1] = Ks[(nf * 8 + g) * STR + ks * 8 + t + 4];
        mma_tf32(s[nf], a, bfr);
      }
    }

    // Causal mask (only the last two tiles can clip)
    if (jt >= 2 * qb) {
      const int r0 = q0 + wrow + g, r1 = r0 + 8;
#pragma unroll
      for (int nf = 0; nf < 8; nf++) {
        int c0 = j0 + nf * 8 + 2 * t, c1 = c0 + 1;
        if (c0 > r0) s[nf][0] = -1e30f;
        if (c1 > r0) s[nf][1] = -1e30f;
        if (c0 > r1) s[nf][2] = -1e30f;
        if (c1 > r1) s[nf][3] = -1e30f;
      }
    }

    // Online softmax, rows r0 (regs 0,1) and r1 (regs 2,3)
    float mx0 = -1e30f, mx1 = -1e30f;
#pragma unroll
    for (int nf = 0; nf < 8; nf++) {
      mx0 = fmaxf(mx0, fmaxf(s[nf][0], s[nf][1]));
      mx1 = fmaxf(mx1, fmaxf(s[nf][2], s[nf][3]));
    }
    mx0 = fmaxf(mx0, __shfl_xor_sync(0xffffffffu, mx0, 1));
    mx0 = fmaxf(mx0, __shfl_xor_sync(0xffffffffu, mx0, 2));
    mx1 = fmaxf(mx1, __shfl_xor_sync(0xffffffffu, mx1, 1));
    mx1 = fmaxf(mx1, __shfl_xor_sync(0xffffffffu, mx1, 2));

    float mn0 = fmaxf(m0, mx0), mn1 = fmaxf(m1, mx1);
    float scl0 = exp2f(m0 - mn0), scl1 = exp2f(m1 - mn1);
    m0 = mn0; m1 = mn1;

    float rs0 = 0.0f, rs1 = 0.0f;
#pragma unroll
    for (int nf = 0; nf < 8; nf++) {
      s[nf][0] = exp2f(s[nf][0] - mn0);
      s[nf][1] = exp2f(s[nf][1] - mn0);
      s[nf][2] = exp2f(s[nf][2] - mn1);
      s[nf][3] = exp2f(s[nf][3] - mn1);
      rs0 += s[nf][0] + s[nf][1];
      rs1 += s[nf][2] + s[nf][3];
      // store P (tf32) for re-fragmentation
      *(float2*)&Ps[(wrow + g) * STR + nf * 8 + 2 * t] =
          make_float2(to_tf32(s[nf][0]), to_tf32(s[nf][1]));
      *(float2*)&Ps[(wrow + g + 8) * STR + nf * 8 + 2 * t] =
          make_float2(to_tf32(s[nf][2]), to_tf32(s[nf][3]));
    }
    rs0 += __shfl_xor_sync(0xffffffffu, rs0, 1);
    rs0 += __shfl_xor_sync(0xffffffffu, rs0, 2);
    rs1 += __shfl_xor_sync(0xffffffffu, rs1, 1);
    rs1 += __shfl_xor_sync(0xffffffffu, rs1, 2);
    l0 = l0 * scl0 + rs0;
    l1 = l1 * scl1 + rs1;

#pragma unroll
    for (int nf = 0; nf < 8; nf++) {
      o[nf][0] *= scl0; o[nf][1] *= scl0;
      o[nf][2] *= scl1; o[nf][3] *= scl1;
    }
    __syncwarp();   // Ps rows of this warp written by this warp only

    // O[16,64] += P_warp @ V : 8 k-steps x 8 n-frags
#pragma unroll
    for (int ks = 0; ks < 8; ks++) {
      float a[4];
      a[0] = Ps[(wrow + g) * STR + ks * 8 + t];
      a[1] = Ps[(wrow + g + 8) * STR + ks * 8 + t];
      a[2] = Ps[(wrow + g) * STR + ks * 8 + t + 4];
      a[3] = Ps[(wrow + g + 8) * STR + ks * 8 + t + 4];
#pragma unroll
      for (int nf = 0; nf < 8; nf++) {
        float bfr[2];
        bfr[0] = Vs[(ks * 8 + t) * STR + nf * 8 + g];
        bfr[1] = Vs[(ks * 8 + t + 4) * STR + nf * 8 + g];
        mma_tf32(o[nf], a, bfr);
      }
    }
  }

  // Normalize and write context
  const float inv0 = 1.0f / l0, inv1 = 1.0f / l1;
  const int r0 = q0 + wrow + g, r1 = r0 + 8;
#pragma unroll
  for (int nf = 0; nf < 8; nf++) {
    int col = nf * 8 + 2 * t;
    *(float2*)(O + base + (size_t)r0 * DMODEL + col) =
        make_float2(o[nf][0] * inv0, o[nf][1] * inv0);
    *(float2*)(O + base + (size_t)r1 * DMODEL + col) =
        make_float2(o[nf][2] * inv1, o[nf][3] * inv1);
  }
}

// ---------------------------------------------------------------------------
extern "C" void kernel_launch(void* const* d_in, const int* in_sizes, int n_in,
                              void* d_out, int out_size) {
  const float* x  = (const float*)d_in[0];
  const float* Wq = (const float*)d_in[1];
  const float* bq = (const float*)d_in[2];
  const float* Wk = (const float*)d_in[3];
  const float* bk = (const float*)d_in[4];
  const float* Wv = (const float*)d_in[5];
  const float* bv = (const float*)d_in[6];
  const float* Wo = (const float*)d_in[7];
  const float* bo = (const float*)d_in[8];
  float* out = (float*)d_out;

  float *Qp, *Kp, *Vp, *Cp, *Ar, *Wr;
  cudaGetSymbolAddress((void**)&Qp, g_Q);
  cudaGetSymbolAddress((void**)&Kp, g_K);
  cudaGetSymbolAddress((void**)&Vp, g_V);
  cudaGetSymbolAddress((void**)&Cp, g_CTX);
  cudaGetSymbolAddress((void**)&Ar, g_Ar);
  cudaGetSymbolAddress((void**)&Wr, g_Wr);

  cudaFuncSetAttribute(flash_attn_tc_kernel,
                       cudaFuncAttributeMaxDynamicSharedMemorySize,
                       ATTN_SMEM_BYTES);
  cudaFuncSetAttribute(gemm_tf32_kernel,
                       cudaFuncAttributeMaxDynamicSharedMemorySize,
                       GT_SMEM_BYTES);

  const int nA4 = M_TOT * DMODEL / 4;
  const int nW4 = DMODEL * DMODEL / 4;
  dim3 ggrid(DMODEL / 128, M_TOT / 128);

  cvt_tf32_kernel<<<nA4 / 256, 256>>>(x, Ar, nA4);

  cvt_tf32_kernel<<<nW4 / 256, 256>>>(Wq, Wr, nW4);
  gemm_tf32_kernel<<<ggrid, 256, GT_SMEM_BYTES>>>(Ar, Wr, bq, Qp);
  cvt_tf32_kernel<<<nW4 / 256, 256>>>(Wk, Wr, nW4);
  gemm_tf32_kernel<<<ggrid, 256, GT_SMEM_BYTES>>>(Ar, Wr, bk, Kp);
  cvt_tf32_kernel<<<nW4 / 256, 256>>>(Wv, Wr, nW4);
  gemm_tf32_kernel<<<ggrid, 256, GT_SMEM_BYTES>>>(Ar, Wr, bv, Vp);

  dim3 attn_grid(S_LEN / BQ, NHEAD, BATCH);   // (16, 16, 2)
  flash_attn_tc_kernel<<<attn_grid, 256, ATTN_SMEM_BYTES>>>(Qp, Kp, Vp, Cp);

  cvt_tf32_kernel<<<nA4 / 256, 256>>>(Cp, Ar, nA4);
  cvt_tf32_kernel<<<nW4 / 256, 256>>>(Wo, Wr, nW4);
  gemm_tf32_kernel<<<ggrid, 256, GT_SMEM_BYTES>>>(Ar, Wr, bo, out);
}

// round 12
// speedup vs baseline: 5.1832x; 1.0373x over previous
#include <cuda_runtime.h>
#include <cstdint>

#define S_LEN  2048
#define DMODEL 1024
#define BATCH  2
#define M_TOT  (BATCH * S_LEN)   // 4096
#define NHEAD  16
#define DHEAD  64
#define LOG2E  1.4426950408889634f

// Scratch (device globals — no allocation in kernel_launch)
__device__ float g_Q[M_TOT * DMODEL];
__device__ float g_K[M_TOT * DMODEL];
__device__ float g_V[M_TOT * DMODEL];
__device__ float g_CTX[M_TOT * DMODEL];
__device__ float g_Ar[M_TOT * DMODEL];        // tf32-rounded x
__device__ float g_Wr0[DMODEL * DMODEL];
__device__ float g_Wr1[DMODEL * DMODEL];
__device__ float g_Wr2[DMODEL * DMODEL];
__device__ float g_Wr3[DMODEL * DMODEL];

// ---------------------------------------------------------------------------
__device__ __forceinline__ float to_tf32(float x) {
  float r;
  asm("cvt.rna.tf32.f32 %0, %1;" : "=f"(r) : "f"(x));
  return r;
}
__device__ __forceinline__ uint32_t smem_u32(const void* p) {
  uint32_t a;
  asm("{ .reg .u64 t; cvta.to.shared.u64 t, %1; cvt.u32.u64 %0, t; }"
      : "=r"(a) : "l"(p));
  return a;
}
__device__ __forceinline__ void cp16(uint32_t s, const void* g) {
  asm volatile("cp.async.cg.shared.global [%0], [%1], 16;"
               :: "r"(s), "l"(g));
}
__device__ __forceinline__ void mma_tf32(float* d, const float* a,
                                         const float* b) {
  asm volatile(
      "mma.sync.aligned.m16n8k8.row.col.f32.tf32.tf32.f32 "
      "{%0,%1,%2,%3}, {%4,%5,%6,%7}, {%8,%9}, {%0,%1,%2,%3};"
      : "+f"(d[0]), "+f"(d[1]), "+f"(d[2]), "+f"(d[3])
      : "r"(__float_as_uint(a[0])), "r"(__float_as_uint(a[1])),
        "r"(__float_as_uint(a[2])), "r"(__float_as_uint(a[3])),
        "r"(__float_as_uint(b[0])), "r"(__float_as_uint(b[1])));
}

// ---------------------------------------------------------------------------
// Elementwise fp32 -> tf32-rounded fp32 (RN), vectorized by 4
// ---------------------------------------------------------------------------
__global__ __launch_bounds__(256) void cvt_tf32_kernel(
    const float* __restrict__ in, float* __restrict__ out, int n4) {
  int i = blockIdx.x * 256 + threadIdx.x;
  if (i >= n4) return;
  float4 v = ((const float4*)in)[i];
  v.x = to_tf32(v.x);
  v.y = to_tf32(v.y);
  v.z = to_tf32(v.z);
  v.w = to_tf32(v.w);
  ((float4*)out)[i] = v;
}

// ---------------------------------------------------------------------------
// tf32 tensor-core GEMM: C = A @ B + bias. round_out: tf32-round the result
// (for tensors consumed by downstream tf32 MMAs).
// ---------------------------------------------------------------------------
#define AS_STRIDE 36
#define BS_STRIDE 132
#define AS_FLOATS (128 * AS_STRIDE)
#define BS_FLOATS (32 * BS_STRIDE)
#define GT_SMEM_BYTES ((2 * AS_FLOATS + 2 * BS_FLOATS) * 4)

__global__ __launch_bounds__(256) void gemm_tf32_kernel(
    const float* __restrict__ A, const float* __restrict__ B,
    const float* __restrict__ bias, float* __restrict__ C, int round_out) {
  extern __shared__ float sm[];
  const uint32_t sbase = smem_u32(sm);

  const int tid = threadIdx.x;
  const int wid = tid >> 5;
  const int lane = tid & 31;
  const int g = lane >> 2;
  const int t = lane & 3;
  const int warp_m = wid & 1;
  const int warp_n = wid >> 1;
  const int row0 = blockIdx.y << 7;
  const int col0 = blockIdx.x << 7;

  float acc[4][4][4] = {};

#define ISSUE(kt)                                                              \
  do {                                                                         \
    int _buf = (kt) & 1;                                                       \
    uint32_t _sA = sbase + _buf * (AS_FLOATS * 4);                             \
    uint32_t _sB = sbase + (2 * AS_FLOATS + _buf * BS_FLOATS) * 4;             \
    _Pragma("unroll") for (int i = 0; i < 4; i++) {                            \
      int idx = tid + 256 * i;                                                 \
      int r = idx >> 3, c4 = idx & 7;                                          \
      cp16(_sA + r * (AS_STRIDE * 4) + c4 * 16,                                \
           A + (size_t)(row0 + r) * DMODEL + (kt) * 32 + c4 * 4);              \
    }                                                                          \
    _Pragma("unroll") for (int i = 0; i < 4; i++) {                            \
      int idx = tid + 256 * i;                                                 \
      int r = idx >> 5, c4 = idx & 31;                                         \
      cp16(_sB + r * (BS_STRIDE * 4) + c4 * 16,                                \
           B + (size_t)((kt) * 32 + r) * DMODEL + col0 + c4 * 4);              \
    }                                                                          \
    asm volatile("cp.async.commit_group;" ::: "memory");                       \
  } while (0)

  ISSUE(0);

  const int NT = DMODEL / 32;
  for (int kt = 0; kt < NT; kt++) {
    if (kt + 1 < NT) {
      ISSUE(kt + 1);
      asm volatile("cp.async.wait_group 1;" ::: "memory");
    } else {
      asm volatile("cp.async.wait_group 0;" ::: "memory");
    }
    __syncthreads();

    const float* as_ = sm + (kt & 1) * AS_FLOATS;
    const float* bs_ = sm + 2 * AS_FLOATS + (kt & 1) * BS_FLOATS;

#pragma unroll
    for (int ks = 0; ks < 4; ks++) {
      float a[4][4], b[4][2];
#pragma unroll
      for (int mf = 0; mf < 4; mf++) {
        int rw = warp_m * 64 + mf * 16 + g;
        int c = ks * 8 + t;
        a[mf][0] = as_[rw * AS_STRIDE + c];
        a[mf][1] = as_[(rw + 8) * AS_STRIDE + c];
        a[mf][2] = as_[rw * AS_STRIDE + c + 4];
        a[mf][3] = as_[(rw + 8) * AS_STRIDE + c + 4];
      }
#pragma unroll
      for (int nf = 0; nf < 4; nf++) {
        int cn = warp_n * 32 + nf * 8 + g;
        int rk = ks * 8 + t;
        b[nf][0] = bs_[rk * BS_STRIDE + cn];
        b[nf][1] = bs_[(rk + 4) * BS_STRIDE + cn];
      }
#pragma unroll
      for (int mf = 0; mf < 4; mf++)
#pragma unroll
        for (int nf = 0; nf < 4; nf++)
          mma_tf32(acc[mf][nf], a[mf], b[nf]);
    }
    __syncthreads();
  }

#pragma unroll
  for (int mf = 0; mf < 4; mf++) {
#pragma unroll
    for (int nf = 0; nf < 4; nf++) {
      int col = col0 + warp_n * 32 + nf * 8 + t * 2;
      float2 bb = *(const float2*)(bias + col);
      int r0 = row0 + warp_m * 64 + mf * 16 + g;
      float2 v0 = make_float2(acc[mf][nf][0] + bb.x, acc[mf][nf][1] + bb.y);
      float2 v1 = make_float2(acc[mf][nf][2] + bb.x, acc[mf][nf][3] + bb.y);
      if (round_out) {
        v0.x = to_tf32(v0.x); v0.y = to_tf32(v0.y);
        v1.x = to_tf32(v1.x); v1.y = to_tf32(v1.y);
      }
      *(float2*)(C + (size_t)r0 * DMODEL + col) = v0;
      *(float2*)(C + (size_t)(r0 + 8) * DMODEL + col) = v1;
    }
  }
#undef ISSUE
}

// ---------------------------------------------------------------------------
// Tensor-core flash attention (tf32 mma.sync, causal).
// Inputs pre-rounded to tf32 by the producing GEMMs -> plain copies here.
// Softmax applies the attention scale: p = exp2((s_raw - m) * C),
// C = (1/sqrt(Dh)) * log2(e). K/V tiles register-prefetched one tile ahead.
// Output CTX written tf32-rounded for the O-projection GEMM.
// ---------------------------------------------------------------------------
#define BQ  128
#define BKV 64
#define STR 72
#define AT_QS 0
#define AT_KS (BQ * STR)
#define AT_VS (AT_KS + BKV * STR)
#define AT_PS (AT_VS + BKV * STR)
#define ATTN_SMEM_FLOATS (AT_PS + BQ * STR)
#define ATTN_SMEM_BYTES  (ATTN_SMEM_FLOATS * 4)   // 110592

__global__ __launch_bounds__(256) void flash_attn_tc_kernel(
    const float* __restrict__ Q, const float* __restrict__ K,
    const float* __restrict__ V, float* __restrict__ O) {
  extern __shared__ float sm[];
  float* Qs = sm + AT_QS;   // [128][72]
  float* Ks = sm + AT_KS;   // [64][72]
  float* Vs = sm + AT_VS;   // [64][72]
  float* Ps = sm + AT_PS;   // [128][72]

  const int tid = threadIdx.x;
  const int wid = tid >> 5;
  const int lane = tid & 31;
  const int g = lane >> 2;
  const int t = lane & 3;
  const int qb = (gridDim.x - 1) - blockIdx.x;   // heavy CTAs first
  const int h  = blockIdx.y;
  const int b  = blockIdx.z;
  const int q0 = qb * BQ;
  const int wrow = wid * 16;

  const size_t base = ((size_t)b * S_LEN) * DMODEL + (size_t)h * DHEAD;
  const float* Qb = Q + base;
  const float* Kb = K + base;
  const float* Vb = V + base;
  const float C = 0.125f * LOG2E;

  // Load Q tile (plain copy; already tf32)
#pragma unroll
  for (int i = 0; i < 8; i++) {
    int idx = tid + 256 * i;
    int r = idx >> 4;
    int c = (idx & 15) << 2;
    *(float4*)&Qs[r * STR + c] =
        *(const float4*)(Qb + (size_t)(q0 + r) * DMODEL + c);
  }

  // Prefetch KV tile 0 into registers
  float4 kreg[4], vreg[4];
#pragma unroll
  for (int i = 0; i < 4; i++) {
    int idx = tid + 256 * i;
    int r = idx >> 4;
    int c = (idx & 15) << 2;
    kreg[i] = *(const float4*)(Kb + (size_t)r * DMODEL + c);
    vreg[i] = *(const float4*)(Vb + (size_t)r * DMODEL + c);
  }

  float m0 = -1e30f, m1 = -1e30f, l0 = 0.0f, l1 = 0.0f;
  float o[8][4] = {};

  const int ntiles = 2 * qb + 2;
  for (int jt = 0; jt < ntiles; jt++) {
    const int jn0 = (jt + 1) * BKV;
    __syncthreads();   // prior tile reads of Ks/Vs done; Q visible (iter 0)

    // Commit prefetched tile to smem
#pragma unroll
    for (int i = 0; i < 4; i++) {
      int idx = tid + 256 * i;
      int r = idx >> 4;
      int c = (idx & 15) << 2;
      *(float4*)&Ks[r * STR + c] = kreg[i];
      *(float4*)&Vs[r * STR + c] = vreg[i];
    }
    __syncthreads();

    // Issue next K tile loads (latency hidden behind S-MMA + softmax)
    if (jt + 1 < ntiles) {
#pragma unroll
      for (int i = 0; i < 4; i++) {
        int idx = tid + 256 * i;
        int r = idx >> 4;
        int c = (idx & 15) << 2;
        kreg[i] = *(const float4*)(Kb + (size_t)(jn0 + r) * DMODEL + c);
      }
    }

    // S[16,64] = Q_warp @ K^T
    float s[8][4] = {};
#pragma unroll
    for (int ks = 0; ks < 8; ks++) {
      float a[4];
      a[0] = Qs[(wrow + g) * STR + ks * 8 + t];
      a[1] = Qs[(wrow + g + 8) * STR + ks * 8 + t];
      a[2] = Qs[(wrow + g) * STR + ks * 8 + t + 4];
      a[3] = Qs[(wrow + g + 8) * STR + ks * 8 + t + 4];
#pragma unroll
      for (int nf = 0; nf < 8; nf++) {
        float bfr[2];
        bfr[0] = Ks[(nf * 8 + g) * STR + ks * 8 + t];
        bfr[1] = Ks[(nf * 8 + g) * STR + ks * 8 + t + 4];
        mma_tf32(s[nf], a, bfr);
      }
    }

    // Causal mask (raw-score units)
    if (jt >= 2 * qb) {
      const int j0 = jt * BKV;
      const int r0 = q0 + wrow + g, r1 = r0 + 8;
#pragma unroll
      for (int nf = 0; nf < 8; nf++) {
        int c0 = j0 + nf * 8 + 2 * t, c1 = c0 + 1;
        if (c0 > r0) s[nf][0] = -1e30f;
        if (c1 > r0) s[nf][1] = -1e30f;
        if (c0 > r1) s[nf][2] = -1e30f;
        if (c1 > r1) s[nf][3] = -1e30f;
      }
    }

    // Online softmax (scale folded into the exponent)
    float mx0 = -1e30f, mx1 = -1e30f;
#pragma unroll
    for (int nf = 0; nf < 8; nf++) {
      mx0 = fmaxf(mx0, fmaxf(s[nf][0], s[nf][1]));
      mx1 = fmaxf(mx1, fmaxf(s[nf][2], s[nf][3]));
    }
    mx0 = fmaxf(mx0, __shfl_xor_sync(0xffffffffu, mx0, 1));
    mx0 = fmaxf(mx0, __shfl_xor_sync(0xffffffffu, mx0, 2));
    mx1 = fmaxf(mx1, __shfl_xor_sync(0xffffffffu, mx1, 1));
    mx1 = fmaxf(mx1, __shfl_xor_sync(0xffffffffu, mx1, 2));

    float mn0 = fmaxf(m0, mx0), mn1 = fmaxf(m1, mx1);
    float scl0 = exp2f((m0 - mn0) * C), scl1 = exp2f((m1 - mn1) * C);
    m0 = mn0; m1 = mn1;

    float rs0 = 0.0f, rs1 = 0.0f;
#pragma unroll
    for (int nf = 0; nf < 8; nf++) {
      s[nf][0] = exp2f((s[nf][0] - mn0) * C);
      s[nf][1] = exp2f((s[nf][1] - mn0) * C);
      s[nf][2] = exp2f((s[nf][2] - mn1) * C);
      s[nf][3] = exp2f((s[nf][3] - mn1) * C);
      rs0 += s[nf][0] + s[nf][1];
      rs1 += s[nf][2] + s[nf][3];
      *(float2*)&Ps[(wrow + g) * STR + nf * 8 + 2 * t] =
          make_float2(to_tf32(s[nf][0]), to_tf32(s[nf][1]));
      *(float2*)&Ps[(wrow + g + 8) * STR + nf * 8 + 2 * t] =
          make_float2(to_tf32(s[nf][2]), to_tf32(s[nf][3]));
    }
    rs0 += __shfl_xor_sync(0xffffffffu, rs0, 1);
    rs0 += __shfl_xor_sync(0xffffffffu, rs0, 2);
    rs1 += __shfl_xor_sync(0xffffffffu, rs1, 1);
    rs1 += __shfl_xor_sync(0xffffffffu, rs1, 2);
    l0 = l0 * scl0 + rs0;
    l1 = l1 * scl1 + rs1;

#pragma unroll
    for (int nf = 0; nf < 8; nf++) {
      o[nf][0] *= scl0; o[nf][1] *= scl0;
      o[nf][2] *= scl1; o[nf][3] *= scl1;
    }
    __syncwarp();   // Ps cross-thread within warp

    // Issue next V tile loads (latency hidden behind PV)
    if (jt + 1 < ntiles) {
#pragma unroll
      for (int i = 0; i < 4; i++) {
        int idx = tid + 256 * i;
        int r = idx >> 4;
        int c = (idx & 15) << 2;
        vreg[i] = *(const float4*)(Vb + (size_t)(jn0 + r) * DMODEL + c);
      }
    }

    // O[16,64] += P_warp @ V
#pragma unroll
    for (int ks = 0; ks < 8; ks++) {
      float a[4];
      a[0] = Ps[(wrow + g) * STR + ks * 8 + t];
      a[1] = Ps[(wrow + g + 8) * STR + ks * 8 + t];
      a[2] = Ps[(wrow + g) * STR + ks * 8 + t + 4];
      a[3] = Ps[(wrow + g + 8) * STR + ks * 8 + t + 4];
#pragma unroll
      for (int nf = 0; nf < 8; nf++) {
        float bfr[2];
        bfr[0] = Vs[(ks * 8 + t) * STR + nf * 8 + g];
        bfr[1] = Vs[(ks * 8 + t + 4) * STR + nf * 8 + g];
        mma_tf32(o[nf], a, bfr);
      }
    }
  }

  // Normalize, tf32-round (consumed by O-projection GEMM), write
  const float inv0 = 1.0f / l0, inv1 = 1.0f / l1;
  const int r0 = q0 + wrow + g, r1 = r0 + 8;
#pragma unroll
  for (int nf = 0; nf < 8; nf++) {
    int col = nf * 8 + 2 * t;
    *(float2*)(O + base + (size_t)r0 * DMODEL + col) =
        make_float2(to_tf32(o[nf][0] * inv0), to_tf32(o[nf][1] * inv0));
    *(float2*)(O + base + (size_t)r1 * DMODEL + col) =
        make_float2(to_tf32(o[nf][2] * inv1), to_tf32(o[nf][3] * inv1));
  }
}

// ---------------------------------------------------------------------------
extern "C" void kernel_launch(void* const* d_in, const int* in_sizes, int n_in,
                              void* d_out, int out_size) {
  const float* x  = (const float*)d_in[0];
  const float* Wq = (const float*)d_in[1];
  const float* bq = (const float*)d_in[2];
  const float* Wk = (const float*)d_in[3];
  const float* bk = (const float*)d_in[4];
  const float* Wv = (const float*)d_in[5];
  const float* bv = (const float*)d_in[6];
  const float* Wo = (const float*)d_in[7];
  const float* bo = (const float*)d_in[8];
  float* out = (float*)d_out;

  float *Qp, *Kp, *Vp, *Cp, *Ar, *W0, *W1, *W2, *W3;
  cudaGetSymbolAddress((void**)&Qp, g_Q);
  cudaGetSymbolAddress((void**)&Kp, g_K);
  cudaGetSymbolAddress((void**)&Vp, g_V);
  cudaGetSymbolAddress((void**)&Cp, g_CTX);
  cudaGetSymbolAddress((void**)&Ar, g_Ar);
  cudaGetSymbolAddress((void**)&W0, g_Wr0);
  cudaGetSymbolAddress((void**)&W1, g_Wr1);
  cudaGetSymbolAddress((void**)&W2, g_Wr2);
  cudaGetSymbolAddress((void**)&W3, g_Wr3);

  cudaFuncSetAttribute(flash_attn_tc_kernel,
                       cudaFuncAttributeMaxDynamicSharedMemorySize,
                       ATTN_SMEM_BYTES);
  cudaFuncSetAttribute(gemm_tf32_kernel,
                       cudaFuncAttributeMaxDynamicSharedMemorySize,
                       GT_SMEM_BYTES);

  const int nA4 = M_TOT * DMODEL / 4;
  const int nW4 = DMODEL * DMODEL / 4;
  dim3 ggrid(DMODEL / 128, M_TOT / 128);

  // All rounding pre-passes up front; GEMMs then run back-to-back.
  cvt_tf32_kernel<<<nA4 / 256, 256>>>(x, Ar, nA4);
  cvt_tf32_kernel<<<nW4 / 256, 256>>>(Wq, W0, nW4);
  cvt_tf32_kernel<<<nW4 / 256, 256>>>(Wk, W1, nW4);
  cvt_tf32_kernel<<<nW4 / 256, 256>>>(Wv, W2, nW4);
  cvt_tf32_kernel<<<nW4 / 256, 256>>>(Wo, W3, nW4);

  gemm_tf32_kernel<<<ggrid, 256, GT_SMEM_BYTES>>>(Ar, W0, bq, Qp, 1);
  gemm_tf32_kernel<<<ggrid, 256, GT_SMEM_BYTES>>>(Ar, W1, bk, Kp, 1);
  gemm_tf32_kernel<<<ggrid, 256, GT_SMEM_BYTES>>>(Ar, W2, bv, Vp, 1);

  dim3 attn_grid(S_LEN / BQ, NHEAD, BATCH);   // (16, 16, 2)
  flash_attn_tc_kernel<<<attn_grid, 256, ATTN_SMEM_BYTES>>>(Qp, Kp, Vp, Cp);

  gemm_tf32_kernel<<<ggrid, 256, GT_SMEM_BYTES>>>(Cp, W3, bo, out, 0);
}

// round 13
// speedup vs baseline: 5.3745x; 1.0369x over previous
#include <cuda_runtime.h>
#include <cstdint>

#define S_LEN  2048
#define DMODEL 1024
#define BATCH  2
#define M_TOT  (BATCH * S_LEN)   // 4096
#define NHEAD  16
#define DHEAD  64
#define LOG2E  1.4426950408889634f

// Scratch (device globals — no allocation in kernel_launch)
__device__ float g_Q[M_TOT * DMODEL];
__device__ float g_K[M_TOT * DMODEL];
__device__ float g_V[M_TOT * DMODEL];
__device__ float g_CTX[M_TOT * DMODEL];
__device__ float g_Ar[M_TOT * DMODEL];        // tf32-rounded x
__device__ float g_Wr0[DMODEL * DMODEL];
__device__ float g_Wr1[DMODEL * DMODEL];
__device__ float g_Wr2[DMODEL * DMODEL];
__device__ float g_Wr3[DMODEL * DMODEL];

// ---------------------------------------------------------------------------
__device__ __forceinline__ float to_tf32(float x) {
  float r;
  asm("cvt.rna.tf32.f32 %0, %1;" : "=f"(r) : "f"(x));
  return r;
}
__device__ __forceinline__ uint32_t smem_u32(const void* p) {
  uint32_t a;
  asm("{ .reg .u64 t; cvta.to.shared.u64 t, %1; cvt.u32.u64 %0, t; }"
      : "=r"(a) : "l"(p));
  return a;
}
__device__ __forceinline__ void cp16(uint32_t s, const void* g) {
  asm volatile("cp.async.cg.shared.global [%0], [%1], 16;"
               :: "r"(s), "l"(g));
}
__device__ __forceinline__ void mma_tf32(float* d, const float* a,
                                         const float* b) {
  asm volatile(
      "mma.sync.aligned.m16n8k8.row.col.f32.tf32.tf32.f32 "
      "{%0,%1,%2,%3}, {%4,%5,%6,%7}, {%8,%9}, {%0,%1,%2,%3};"
      : "+f"(d[0]), "+f"(d[1]), "+f"(d[2]), "+f"(d[3])
      : "r"(__float_as_uint(a[0])), "r"(__float_as_uint(a[1])),
        "r"(__float_as_uint(a[2])), "r"(__float_as_uint(a[3])),
        "r"(__float_as_uint(b[0])), "r"(__float_as_uint(b[1])));
}

// ---------------------------------------------------------------------------
// Fused tf32-rounding pass: x (1M float4) + 4 weight matrices (256K each).
// ---------------------------------------------------------------------------
#define NA4 (M_TOT * DMODEL / 4)     // 1048576
#define NW4 (DMODEL * DMODEL / 4)    // 262144 = 1<<18

__global__ __launch_bounds__(256) void cvt_all_kernel(
    const float* __restrict__ x, float* __restrict__ Ar,
    const float* __restrict__ w0, float* __restrict__ o0,
    const float* __restrict__ w1, float* __restrict__ o1,
    const float* __restrict__ w2, float* __restrict__ o2,
    const float* __restrict__ w3, float* __restrict__ o3) {
  int i = blockIdx.x * 256 + threadIdx.x;
  const float4* in;
  float4* out;
  int off;
  if (i < NA4) {
    in = (const float4*)x; out = (float4*)Ar; off = i;
  } else {
    int j = i - NA4;
    int seg = j >> 18;
    off = j & (NW4 - 1);
    switch (seg) {
      case 0:  in = (const float4*)w0; out = (float4*)o0; break;
      case 1:  in = (const float4*)w1; out = (float4*)o1; break;
      case 2:  in = (const float4*)w2; out = (float4*)o2; break;
      default: in = (const float4*)w3; out = (float4*)o3; break;
    }
  }
  float4 v = in[off];
  v.x = to_tf32(v.x);
  v.y = to_tf32(v.y);
  v.z = to_tf32(v.z);
  v.w = to_tf32(v.w);
  out[off] = v;
}

// ---------------------------------------------------------------------------
// tf32 tensor-core GEMM body (shared by QKV-fused and O-projection kernels).
// 128x128 CTA tile, BK=32, cp.async double buffer, 8 warps.
// ---------------------------------------------------------------------------
#define AS_STRIDE 36
#define BS_STRIDE 132
#define AS_FLOATS (128 * AS_STRIDE)
#define BS_FLOATS (32 * BS_STRIDE)
#define GT_SMEM_BYTES ((2 * AS_FLOATS + 2 * BS_FLOATS) * 4)

__device__ __forceinline__ void gemm_body(
    const float* __restrict__ A, const float* __restrict__ B,
    const float* __restrict__ bias, float* __restrict__ C,
    int row0, int col0, int round_out, float* sm) {
  const uint32_t sbase = smem_u32(sm);
  const int tid = threadIdx.x;
  const int wid = tid >> 5;
  const int lane = tid & 31;
  const int g = lane >> 2;
  const int t = lane & 3;
  const int warp_m = wid & 1;
  const int warp_n = wid >> 1;

  float acc[4][4][4] = {};

#define ISSUE(kt)                                                              \
  do {                                                                         \
    int _buf = (kt) & 1;                                                       \
    uint32_t _sA = sbase + _buf * (AS_FLOATS * 4);                             \
    uint32_t _sB = sbase + (2 * AS_FLOATS + _buf * BS_FLOATS) * 4;             \
    _Pragma("unroll") for (int i = 0; i < 4; i++) {                            \
      int idx = tid + 256 * i;                                                 \
      int r = idx >> 3, c4 = idx & 7;                                          \
      cp16(_sA + r * (AS_STRIDE * 4) + c4 * 16,                                \
           A + (size_t)(row0 + r) * DMODEL + (kt) * 32 + c4 * 4);              \
    }                                                                          \
    _Pragma("unroll") for (int i = 0; i < 4; i++) {                            \
      int idx = tid + 256 * i;                                                 \
      int r = idx >> 5, c4 = idx & 31;                                         \
      cp16(_sB + r * (BS_STRIDE * 4) + c4 * 16,                                \
           B + (size_t)((kt) * 32 + r) * DMODEL + col0 + c4 * 4);              \
    }                                                                          \
    asm volatile("cp.async.commit_group;" ::: "memory");                       \
  } while (0)

  ISSUE(0);

  const int NT = DMODEL / 32;
  for (int kt = 0; kt < NT; kt++) {
    if (kt + 1 < NT) {
      ISSUE(kt + 1);
      asm volatile("cp.async.wait_group 1;" ::: "memory");
    } else {
      asm volatile("cp.async.wait_group 0;" ::: "memory");
    }
    __syncthreads();

    const float* as_ = sm + (kt & 1) * AS_FLOATS;
    const float* bs_ = sm + 2 * AS_FLOATS + (kt & 1) * BS_FLOATS;

#pragma unroll
    for (int ks = 0; ks < 4; ks++) {
      float a[4][4], b[4][2];
#pragma unroll
      for (int mf = 0; mf < 4; mf++) {
        int rw = warp_m * 64 + mf * 16 + g;
        int c = ks * 8 + t;
        a[mf][0] = as_[rw * AS_STRIDE + c];
        a[mf][1] = as_[(rw + 8) * AS_STRIDE + c];
        a[mf][2] = as_[rw * AS_STRIDE + c + 4];
        a[mf][3] = as_[(rw + 8) * AS_STRIDE + c + 4];
      }
#pragma unroll
      for (int nf = 0; nf < 4; nf++) {
        int cn = warp_n * 32 + nf * 8 + g;
        int rk = ks * 8 + t;
        b[nf][0] = bs_[rk * BS_STRIDE + cn];
        b[nf][1] = bs_[(rk + 4) * BS_STRIDE + cn];
      }
#pragma unroll
      for (int mf = 0; mf < 4; mf++)
#pragma unroll
        for (int nf = 0; nf < 4; nf++)
          mma_tf32(acc[mf][nf], a[mf], b[nf]);
    }
    __syncthreads();
  }

#pragma unroll
  for (int mf = 0; mf < 4; mf++) {
#pragma unroll
    for (int nf = 0; nf < 4; nf++) {
      int col = col0 + warp_n * 32 + nf * 8 + t * 2;
      float2 bb = *(const float2*)(bias + col);
      int r0 = row0 + warp_m * 64 + mf * 16 + g;
      float2 v0 = make_float2(acc[mf][nf][0] + bb.x, acc[mf][nf][1] + bb.y);
      float2 v1 = make_float2(acc[mf][nf][2] + bb.x, acc[mf][nf][3] + bb.y);
      if (round_out) {
        v0.x = to_tf32(v0.x); v0.y = to_tf32(v0.y);
        v1.x = to_tf32(v1.x); v1.y = to_tf32(v1.y);
      }
      *(float2*)(C + (size_t)r0 * DMODEL + col) = v0;
      *(float2*)(C + (size_t)(r0 + 8) * DMODEL + col) = v1;
    }
  }
#undef ISSUE
}

// Fused Q/K/V projection: grid.x = 24 (8 col-tiles x 3 matrices), grid.y = 32.
__global__ __launch_bounds__(256) void gemm_qkv_kernel(
    const float* __restrict__ A,
    const float* __restrict__ B0, const float* __restrict__ B1,
    const float* __restrict__ B2,
    const float* __restrict__ bias0, const float* __restrict__ bias1,
    const float* __restrict__ bias2,
    float* __restrict__ C0, float* __restrict__ C1, float* __restrict__ C2) {
  extern __shared__ float sm[];
  const int sel = blockIdx.x >> 3;
  const int col0 = (blockIdx.x & 7) << 7;
  const int row0 = blockIdx.y << 7;
  const float* B = (sel == 0) ? B0 : (sel == 1) ? B1 : B2;
  const float* bias = (sel == 0) ? bias0 : (sel == 1) ? bias1 : bias2;
  float* C = (sel == 0) ? C0 : (sel == 1) ? C1 : C2;
  gemm_body(A, B, bias, C, row0, col0, 1, sm);
}

// Single GEMM (O-projection, raw fp32 output).
__global__ __launch_bounds__(256) void gemm_tf32_kernel(
    const float* __restrict__ A, const float* __restrict__ B,
    const float* __restrict__ bias, float* __restrict__ C, int round_out) {
  extern __shared__ float sm[];
  gemm_body(A, B, bias, C, blockIdx.y << 7, blockIdx.x << 7, round_out, sm);
}

// ---------------------------------------------------------------------------
// Tensor-core flash attention (tf32 mma.sync, causal) — unchanged from R12.
// ---------------------------------------------------------------------------
#define BQ  128
#define BKV 64
#define STR 72
#define AT_QS 0
#define AT_KS (BQ * STR)
#define AT_VS (AT_KS + BKV * STR)
#define AT_PS (AT_VS + BKV * STR)
#define ATTN_SMEM_FLOATS (AT_PS + BQ * STR)
#define ATTN_SMEM_BYTES  (ATTN_SMEM_FLOATS * 4)   // 110592

__global__ __launch_bounds__(256) void flash_attn_tc_kernel(
    const float* __restrict__ Q, const float* __restrict__ K,
    const float* __restrict__ V, float* __restrict__ O) {
  extern __shared__ float sm[];
  float* Qs = sm + AT_QS;
  float* Ks = sm + AT_KS;
  float* Vs = sm + AT_VS;
  float* Ps = sm + AT_PS;

  const int tid = threadIdx.x;
  const int wid = tid >> 5;
  const int lane = tid & 31;
  const int g = lane >> 2;
  const int t = lane & 3;
  const int qb = (gridDim.x - 1) - blockIdx.x;
  const int h  = blockIdx.y;
  const int b  = blockIdx.z;
  const int q0 = qb * BQ;
  const int wrow = wid * 16;

  const size_t base = ((size_t)b * S_LEN) * DMODEL + (size_t)h * DHEAD;
  const float* Qb = Q + base;
  const float* Kb = K + base;
  const float* Vb = V + base;
  const float C = 0.125f * LOG2E;

#pragma unroll
  for (int i = 0; i < 8; i++) {
    int idx = tid + 256 * i;
    int r = idx >> 4;
    int c = (idx & 15) << 2;
    *(float4*)&Qs[r * STR + c] =
        *(const float4*)(Qb + (size_t)(q0 + r) * DMODEL + c);
  }

  float4 kreg[4], vreg[4];
#pragma unroll
  for (int i = 0; i < 4; i++) {
    int idx = tid + 256 * i;
    int r = idx >> 4;
    int c = (idx & 15) << 2;
    kreg[i] = *(const float4*)(Kb + (size_t)r * DMODEL + c);
    vreg[i] = *(const float4*)(Vb + (size_t)r * DMODEL + c);
  }

  float m0 = -1e30f, m1 = -1e30f, l0 = 0.0f, l1 = 0.0f;
  float o[8][4] = {};

  const int ntiles = 2 * qb + 2;
  for (int jt = 0; jt < ntiles; jt++) {
    const int jn0 = (jt + 1) * BKV;
    __syncthreads();

#pragma unroll
    for (int i = 0; i < 4; i++) {
      int idx = tid + 256 * i;
      int r = idx >> 4;
      int c = (idx & 15) << 2;
      *(float4*)&Ks[r * STR + c] = kreg[i];
      *(float4*)&Vs[r * STR + c] = vreg[i];
    }
    __syncthreads();

    if (jt + 1 < ntiles) {
#pragma unroll
      for (int i = 0; i < 4; i++) {
        int idx = tid + 256 * i;
        int r = idx >> 4;
        int c = (idx & 15) << 2;
        kreg[i] = *(const float4*)(Kb + (size_t)(jn0 + r) * DMODEL + c);
      }
    }

    float s[8][4] = {};
#pragma unroll
    for (int ks = 0; ks < 8; ks++) {
      float a[4];
      a[0] = Qs[(wrow + g) * STR + ks * 8 + t];
      a[1] = Qs[(wrow + g + 8) * STR + ks * 8 + t];
      a[2] = Qs[(wrow + g) * STR + ks * 8 + t + 4];
      a[3] = Qs[(wrow + g + 8) * STR + ks * 8 + t + 4];
#pragma unroll
      for (int nf = 0; nf < 8; nf++) {
        float bfr[2];
        bfr[0] = Ks[(nf * 8 + g) * STR + ks * 8 + t];
        bfr[1] = Ks[(nf * 8 + g) * STR + ks * 8 + t + 4];
        mma_tf32(s[nf], a, bfr);
      }
    }

    if (jt >= 2 * qb) {
      const int j0 = jt * BKV;
      const int r0 = q0 + wrow + g, r1 = r0 + 8;
#pragma unroll
      for (int nf = 0; nf < 8; nf++) {
        int c0 = j0 + nf * 8 + 2 * t, c1 = c0 + 1;
        if (c0 > r0) s[nf][0] = -1e30f;
        if (c1 > r0) s[nf][1] = -1e30f;
        if (c0 > r1) s[nf][2] = -1e30f;
        if (c1 > r1) s[nf][3] = -1e30f;
      }
    }

    float mx0 = -1e30f, mx1 = -1e30f;
#pragma unroll
    for (int nf = 0; nf < 8; nf++) {
      mx0 = fmaxf(mx0, fmaxf(s[nf][0], s[nf][1]));
      mx1 = fmaxf(mx1, fmaxf(s[nf][2], s[nf][3]));
    }
    mx0 = fmaxf(mx0, __shfl_xor_sync(0xffffffffu, mx0, 1));
    mx0 = fmaxf(mx0, __shfl_xor_sync(0xffffffffu, mx0, 2));
    mx1 = fmaxf(mx1, __shfl_xor_sync(0xffffffffu, mx1, 1));
    mx1 = fmaxf(mx1, __shfl_xor_sync(0xffffffffu, mx1, 2));

    float mn0 = fmaxf(m0, mx0), mn1 = fmaxf(m1, mx1);
    float scl0 = exp2f((m0 - mn0) * C), scl1 = exp2f((m1 - mn1) * C);
    m0 = mn0; m1 = mn1;

    float rs0 = 0.0f, rs1 = 0.0f;
#pragma unroll
    for (int nf = 0; nf < 8; nf++) {
      s[nf][0] = exp2f((s[nf][0] - mn0) * C);
      s[nf][1] = exp2f((s[nf][1] - mn0) * C);
      s[nf][2] = exp2f((s[nf][2] - mn1) * C);
      s[nf][3] = exp2f((s[nf][3] - mn1) * C);
      rs0 += s[nf][0] + s[nf][1];
      rs1 += s[nf][2] + s[nf][3];
      *(float2*)&Ps[(wrow + g) * STR + nf * 8 + 2 * t] =
          make_float2(to_tf32(s[nf][0]), to_tf32(s[nf][1]));
      *(float2*)&Ps[(wrow + g + 8) * STR + nf * 8 + 2 * t] =
          make_float2(to_tf32(s[nf][2]), to_tf32(s[nf][3]));
    }
    rs0 += __shfl_xor_sync(0xffffffffu, rs0, 1);
    rs0 += __shfl_xor_sync(0xffffffffu, rs0, 2);
    rs1 += __shfl_xor_sync(0xffffffffu, rs1, 1);
    rs1 += __shfl_xor_sync(0xffffffffu, rs1, 2);
    l0 = l0 * scl0 + rs0;
    l1 = l1 * scl1 + rs1;

#pragma unroll
    for (int nf = 0; nf < 8; nf++) {
      o[nf][0] *= scl0; o[nf][1] *= scl0;
      o[nf][2] *= scl1; o[nf][3] *= scl1;
    }
    __syncwarp();

    if (jt + 1 < ntiles) {
#pragma unroll
      for (int i = 0; i < 4; i++) {
        int idx = tid + 256 * i;
        int r = idx >> 4;
        int c = (idx & 15) << 2;
        vreg[i] = *(const float4*)(Vb + (size_t)(jn0 + r) * DMODEL + c);
      }
    }

#pragma unroll
    for (int ks = 0; ks < 8; ks++) {
      float a[4];
      a[0] = Ps[(wrow + g) * STR + ks * 8 + t];
      a[1] = Ps[(wrow + g + 8) * STR + ks * 8 + t];
      a[2] = Ps[(wrow + g) * STR + ks * 8 + t + 4];
      a[3] = Ps[(wrow + g + 8) * STR + ks * 8 + t + 4];
#pragma unroll
      for (int nf = 0; nf < 8; nf++) {
        float bfr[2];
        bfr[0] = Vs[(ks * 8 + t) * STR + nf * 8 + g];
        bfr[1] = Vs[(ks * 8 + t + 4) * STR + nf * 8 + g];
        mma_tf32(o[nf], a, bfr);
      }
    }
  }

  const float inv0 = 1.0f / l0, inv1 = 1.0f / l1;
  const int r0 = q0 + wrow + g, r1 = r0 + 8;
#pragma unroll
  for (int nf = 0; nf < 8; nf++) {
    int col = nf * 8 + 2 * t;
    *(float2*)(O + base + (size_t)r0 * DMODEL + col) =
        make_float2(to_tf32(o[nf][0] * inv0), to_tf32(o[nf][1] * inv0));
    *(float2*)(O + base + (size_t)r1 * DMODEL + col) =
        make_float2(to_tf32(o[nf][2] * inv1), to_tf32(o[nf][3] * inv1));
  }
}

// ---------------------------------------------------------------------------
extern "C" void kernel_launch(void* const* d_in, const int* in_sizes, int n_in,
                              void* d_out, int out_size) {
  const float* x  = (const float*)d_in[0];
  const float* Wq = (const float*)d_in[1];
  const float* bq = (const float*)d_in[2];
  const float* Wk = (const float*)d_in[3];
  const float* bk = (const float*)d_in[4];
  const float* Wv = (const float*)d_in[5];
  const float* bv = (const float*)d_in[6];
  const float* Wo = (const float*)d_in[7];
  const float* bo = (const float*)d_in[8];
  float* out = (float*)d_out;

  float *Qp, *Kp, *Vp, *Cp, *Ar, *W0, *W1, *W2, *W3;
  cudaGetSymbolAddress((void**)&Qp, g_Q);
  cudaGetSymbolAddress((void**)&Kp, g_K);
  cudaGetSymbolAddress((void**)&Vp, g_V);
  cudaGetSymbolAddress((void**)&Cp, g_CTX);
  cudaGetSymbolAddress((void**)&Ar, g_Ar);
  cudaGetSymbolAddress((void**)&W0, g_Wr0);
  cudaGetSymbolAddress((void**)&W1, g_Wr1);
  cudaGetSymbolAddress((void**)&W2, g_Wr2);
  cudaGetSymbolAddress((void**)&W3, g_Wr3);

  cudaFuncSetAttribute(flash_attn_tc_kernel,
                       cudaFuncAttributeMaxDynamicSharedMemorySize,
                       ATTN_SMEM_BYTES);
  cudaFuncSetAttribute(gemm_qkv_kernel,
                       cudaFuncAttributeMaxDynamicSharedMemorySize,
                       GT_SMEM_BYTES);
  cudaFuncSetAttribute(gemm_tf32_kernel,
                       cudaFuncAttributeMaxDynamicSharedMemorySize,
                       GT_SMEM_BYTES);

  // Single rounding pass for x + all weights
  const int ncvt = NA4 + 4 * NW4;   // 2M float4s
  cvt_all_kernel<<<ncvt / 256, 256>>>(x, Ar, Wq, W0, Wk, W1, Wv, W2, Wo, W3);

  // Fused Q/K/V projections: 768 CTAs in one launch
  dim3 qkv_grid(24, M_TOT / 128);   // (24, 32)
  gemm_qkv_kernel<<<qkv_grid, 256, GT_SMEM_BYTES>>>(
      Ar, W0, W1, W2, bq, bk, bv, Qp, Kp, Vp);

  dim3 attn_grid(S_LEN / BQ, NHEAD, BATCH);   // (16, 16, 2)
  flash_attn_tc_kernel<<<attn_grid, 256, ATTN_SMEM_BYTES>>>(Qp, Kp, Vp, Cp);

  dim3 ggrid(DMODEL / 128, M_TOT / 128);      // (8, 32)
  gemm_tf32_kernel<<<ggrid, 256, GT_SMEM_BYTES>>>(Cp, W3, bo, out, 0);
}

// round 15
// speedup vs baseline: 5.5031x; 1.0239x over previous
#include <cuda_runtime.h>
#include <cstdint>

#define S_LEN  2048
#define DMODEL 1024
#define BATCH  2
#define M_TOT  (BATCH * S_LEN)   // 4096
#define NHEAD  16
#define DHEAD  64
#define LOG2E  1.4426950408889634f

// Scratch (device globals — no allocation in kernel_launch)
__device__ float g_Q[M_TOT * DMODEL];
__device__ float g_K[M_TOT * DMODEL];
__device__ float g_V[M_TOT * DMODEL];
__device__ float g_CTX[M_TOT * DMODEL];
__device__ float g_Ar[M_TOT * DMODEL];        // tf32-rounded x
__device__ float g_Wr0[DMODEL * DMODEL];
__device__ float g_Wr1[DMODEL * DMODEL];
__device__ float g_Wr2[DMODEL * DMODEL];
__device__ float g_Wr3[DMODEL * DMODEL];

// ---------------------------------------------------------------------------
__device__ __forceinline__ float to_tf32(float x) {
  float r;
  asm("cvt.rna.tf32.f32 %0, %1;" : "=f"(r) : "f"(x));
  return r;
}
__device__ __forceinline__ uint32_t smem_u32(const void* p) {
  uint32_t a;
  asm("{ .reg .u64 t; cvta.to.shared.u64 t, %1; cvt.u32.u64 %0, t; }"
      : "=r"(a) : "l"(p));
  return a;
}
__device__ __forceinline__ void cp16(uint32_t s, const void* g) {
  asm volatile("cp.async.cg.shared.global [%0], [%1], 16;"
               :: "r"(s), "l"(g));
}
__device__ __forceinline__ void mma_tf32(float* d, const float* a,
                                         const float* b) {
  asm volatile(
      "mma.sync.aligned.m16n8k8.row.col.f32.tf32.tf32.f32 "
      "{%0,%1,%2,%3}, {%4,%5,%6,%7}, {%8,%9}, {%0,%1,%2,%3};"
      : "+f"(d[0]), "+f"(d[1]), "+f"(d[2]), "+f"(d[3])
      : "r"(__float_as_uint(a[0])), "r"(__float_as_uint(a[1])),
        "r"(__float_as_uint(a[2])), "r"(__float_as_uint(a[3])),
        "r"(__float_as_uint(b[0])), "r"(__float_as_uint(b[1])));
}

// ---------------------------------------------------------------------------
// Fused tf32-rounding pass: x (1M float4) + 4 weight matrices (256K each).
// ---------------------------------------------------------------------------
#define NA4 (M_TOT * DMODEL / 4)     // 1048576
#define NW4 (DMODEL * DMODEL / 4)    // 262144 = 1<<18

__global__ __launch_bounds__(256) void cvt_all_kernel(
    const float* __restrict__ x, float* __restrict__ Ar,
    const float* __restrict__ w0, float* __restrict__ o0,
    const float* __restrict__ w1, float* __restrict__ o1,
    const float* __restrict__ w2, float* __restrict__ o2,
    const float* __restrict__ w3, float* __restrict__ o3) {
  int i = blockIdx.x * 256 + threadIdx.x;
  const float4* in;
  float4* out;
  int off;
  if (i < NA4) {
    in = (const float4*)x; out = (float4*)Ar; off = i;
  } else {
    int j = i - NA4;
    int seg = j >> 18;
    off = j & (NW4 - 1);
    switch (seg) {
      case 0:  in = (const float4*)w0; out = (float4*)o0; break;
      case 1:  in = (const float4*)w1; out = (float4*)o1; break;
      case 2:  in = (const float4*)w2; out = (float4*)o2; break;
      default: in = (const float4*)w3; out = (float4*)o3; break;
    }
  }
  float4 v = in[off];
  v.x = to_tf32(v.x);
  v.y = to_tf32(v.y);
  v.z = to_tf32(v.z);
  v.w = to_tf32(v.w);
  out[off] = v;
}

// ---------------------------------------------------------------------------
// tf32 tensor-core GEMM body. 128x128 CTA tile, BK=32, 3-stage cp.async
// pipeline (2 chunks always in flight), 8 warps.
// ---------------------------------------------------------------------------
#define AS_STRIDE 36
#define BS_STRIDE 132
#define AS_FLOATS (128 * AS_STRIDE)          // 4608
#define BS_FLOATS (32 * BS_STRIDE)           // 4224
#define GT_SMEM_BYTES (3 * (AS_FLOATS + BS_FLOATS) * 4)   // 105984

__device__ __forceinline__ void gemm_body(
    const float* __restrict__ A, const float* __restrict__ B,
    const float* __restrict__ bias, float* __restrict__ C,
    int row0, int col0, int round_out, float* sm) {
  const uint32_t sbase = smem_u32(sm);
  const int tid = threadIdx.x;
  const int wid = tid >> 5;
  const int lane = tid & 31;
  const int g = lane >> 2;
  const int t = lane & 3;
  const int warp_m = wid & 1;
  const int warp_n = wid >> 1;

  float acc[4][4][4] = {};

#define ISSUE(kt, buf)                                                         \
  do {                                                                         \
    uint32_t _sA = sbase + (buf) * (AS_FLOATS * 4);                            \
    uint32_t _sB = sbase + (3 * AS_FLOATS + (buf) * BS_FLOATS) * 4;            \
    _Pragma("unroll") for (int i = 0; i < 4; i++) {                            \
      int idx = tid + 256 * i;                                                 \
      int r = idx >> 3, c4 = idx & 7;                                          \
      cp16(_sA + r * (AS_STRIDE * 4) + c4 * 16,                                \
           A + (size_t)(row0 + r) * DMODEL + (kt) * 32 + c4 * 4);              \
    }                                                                          \
    _Pragma("unroll") for (int i = 0; i < 4; i++) {                            \
      int idx = tid + 256 * i;                                                 \
      int r = idx >> 5, c4 = idx & 31;                                         \
      cp16(_sB + r * (BS_STRIDE * 4) + c4 * 16,                                \
           B + (size_t)((kt) * 32 + r) * DMODEL + col0 + c4 * 4);              \
    }                                                                          \
    asm volatile("cp.async.commit_group;" ::: "memory");                       \
  } while (0)

  ISSUE(0, 0);
  ISSUE(1, 1);

  const int NT = DMODEL / 32;   // 32
  for (int kt = 0; kt < NT; kt++) {
    const int buf = kt % 3;
    if (kt + 2 < NT) {
      ISSUE(kt + 2, (kt + 2) % 3);
      asm volatile("cp.async.wait_group 2;" ::: "memory");
    } else if (kt + 1 < NT) {
      asm volatile("cp.async.wait_group 1;" ::: "memory");
    } else {
      asm volatile("cp.async.wait_group 0;" ::: "memory");
    }
    __syncthreads();

    const float* as_ = sm + buf * AS_FLOATS;
    const float* bs_ = sm + 3 * AS_FLOATS + buf * BS_FLOATS;

#pragma unroll
    for (int ks = 0; ks < 4; ks++) {
      float a[4][4], b[4][2];
#pragma unroll
      for (int mf = 0; mf < 4; mf++) {
        int rw = warp_m * 64 + mf * 16 + g;
        int c = ks * 8 + t;
        a[mf][0] = as_[rw * AS_STRIDE + c];
        a[mf][1] = as_[(rw + 8) * AS_STRIDE + c];
        a[mf][2] = as_[rw * AS_STRIDE + c + 4];
        a[mf][3] = as_[(rw + 8) * AS_STRIDE + c + 4];
      }
#pragma unroll
      for (int nf = 0; nf < 4; nf++) {
        int cn = warp_n * 32 + nf * 8 + g;
        int rk = ks * 8 + t;
        b[nf][0] = bs_[rk * BS_STRIDE + cn];
        b[nf][1] = bs_[(rk + 4) * BS_STRIDE + cn];
      }
#pragma unroll
      for (int mf = 0; mf < 4; mf++)
#pragma unroll
        for (int nf = 0; nf < 4; nf++)
          mma_tf32(acc[mf][nf], a[mf], b[nf]);
    }
    __syncthreads();   // stage `buf` free for reuse (overwritten at kt+1's ISSUE)
  }

#pragma unroll
  for (int mf = 0; mf < 4; mf++) {
#pragma unroll
    for (int nf = 0; nf < 4; nf++) {
      int col = col0 + warp_n * 32 + nf * 8 + t * 2;
      float2 bb = *(const float2*)(bias + col);
      int r0 = row0 + warp_m * 64 + mf * 16 + g;
      float2 v0 = make_float2(acc[mf][nf][0] + bb.x, acc[mf][nf][1] + bb.y);
      float2 v1 = make_float2(acc[mf][nf][2] + bb.x, acc[mf][nf][3] + bb.y);
      if (round_out) {
        v0.x = to_tf32(v0.x); v0.y = to_tf32(v0.y);
        v1.x = to_tf32(v1.x); v1.y = to_tf32(v1.y);
      }
      *(float2*)(C + (size_t)r0 * DMODEL + col) = v0;
      *(float2*)(C + (size_t)(r0 + 8) * DMODEL + col) = v1;
    }
  }
#undef ISSUE
}

// Fused Q/K/V projection: grid.x = 24 (8 col-tiles x 3 matrices), grid.y = 32.
__global__ __launch_bounds__(256) void gemm_qkv_kernel(
    const float* __restrict__ A,
    const float* __restrict__ B0, const float* __restrict__ B1,
    const float* __restrict__ B2,
    const float* __restrict__ bias0, const float* __restrict__ bias1,
    const float* __restrict__ bias2,
    float* __restrict__ C0, float* __restrict__ C1, float* __restrict__ C2) {
  extern __shared__ float sm[];
  const int sel = blockIdx.x >> 3;
  const int col0 = (blockIdx.x & 7) << 7;
  const int row0 = blockIdx.y << 7;
  const float* B = (sel == 0) ? B0 : (sel == 1) ? B1 : B2;
  const float* bias = (sel == 0) ? bias0 : (sel == 1) ? bias1 : bias2;
  float* C = (sel == 0) ? C0 : (sel == 1) ? C1 : C2;
  gemm_body(A, B, bias, C, row0, col0, 1, sm);
}

// Single GEMM (O-projection, raw fp32 output).
__global__ __launch_bounds__(256) void gemm_tf32_kernel(
    const float* __restrict__ A, const float* __restrict__ B,
    const float* __restrict__ bias, float* __restrict__ C, int round_out) {
  extern __shared__ float sm[];
  gemm_body(A, B, bias, C, blockIdx.y << 7, blockIdx.x << 7, round_out, sm);
}

// ---------------------------------------------------------------------------
// Tensor-core flash attention (tf32 mma.sync, causal).
// Q fragments hoisted to registers (staging buffer aliased as Ps).
// K/V double-buffered via cp.async (no register round trip).
// ---------------------------------------------------------------------------
#define BQ  128
#define BKV 64
#define STR 72
#define KV_FLOATS (BKV * STR)                 // 4608 per buffer
#define AT_PS (4 * KV_FLOATS)                 // 18432
#define ATTN_SMEM_FLOATS (AT_PS + BQ * STR)   // 27648
#define ATTN_SMEM_BYTES  (ATTN_SMEM_FLOATS * 4)  // 110592

__global__ __launch_bounds__(256) void flash_attn_tc_kernel(
    const float* __restrict__ Q, const float* __restrict__ K,
    const float* __restrict__ V, float* __restrict__ O) {
  extern __shared__ float sm[];
  // KV buffers: K0, K1, V0, V1 ; Ps aliases the Q staging region.
  float* Ps = sm + AT_PS;

  const int tid = threadIdx.x;
  const int wid = tid >> 5;
  const int lane = tid & 31;
  const int g = lane >> 2;
  const int t = lane & 3;
  const int qb = (gridDim.x - 1) - blockIdx.x;   // heavy CTAs first
  const int h  = blockIdx.y;
  const int b  = blockIdx.z;
  const int q0 = qb * BQ;
  const int wrow = wid * 16;

  const size_t base = ((size_t)b * S_LEN) * DMODEL + (size_t)h * DHEAD;
  const float* Qb = Q + base;
  const float* Kb = K + base;
  const float* Vb = V + base;
  const uint32_t sbase = smem_u32(sm);
  const float C = 0.125f * LOG2E;

#define KV_ISSUE(jt, buf)                                                      \
  do {                                                                         \
    int _j0 = (jt) * BKV;                                                      \
    uint32_t _sk = sbase + (buf) * (KV_FLOATS * 4);                            \
    uint32_t _sv = sbase + (2 + (buf)) * (KV_FLOATS * 4);                      \
    _Pragma("unroll") for (int i = 0; i < 4; i++) {                            \
      int idx = tid + 256 * i;                                                 \
      int r = idx >> 4;                                                        \
      int c = (idx & 15) << 2;                                                 \
      cp16(_sk + (r * STR + c) * 4, Kb + (size_t)(_j0 + r) * DMODEL + c);      \
      cp16(_sv + (r * STR + c) * 4, Vb + (size_t)(_j0 + r) * DMODEL + c);      \
    }                                                                          \
    asm volatile("cp.async.commit_group;" ::: "memory");                       \
  } while (0)

  // Stage Q through the Ps region, then hoist fragments to registers.
#pragma unroll
  for (int i = 0; i < 8; i++) {
    int idx = tid + 256 * i;
    int r = idx >> 4;
    int c = (idx & 15) << 2;
    *(float4*)&Ps[r * STR + c] =
        *(const float4*)(Qb + (size_t)(q0 + r) * DMODEL + c);
  }
  // Kick off KV tile 0 while Q staging settles.
  KV_ISSUE(0, 0);
  __syncthreads();

  float qf[8][4];
#pragma unroll
  for (int ks = 0; ks < 8; ks++) {
    qf[ks][0] = Ps[(wrow + g) * STR + ks * 8 + t];
    qf[ks][1] = Ps[(wrow + g + 8) * STR + ks * 8 + t];
    qf[ks][2] = Ps[(wrow + g) * STR + ks * 8 + t + 4];
    qf[ks][3] = Ps[(wrow + g + 8) * STR + ks * 8 + t + 4];
  }
  __syncthreads();   // all warps done reading Q staging; Ps region reusable

  float m0 = -1e30f, m1 = -1e30f, l0 = 0.0f, l1 = 0.0f;
  float o[8][4] = {};

  const int ntiles = 2 * qb + 2;
  for (int jt = 0; jt < ntiles; jt++) {
    const int buf = jt & 1;
    if (jt + 1 < ntiles) {
      KV_ISSUE(jt + 1, buf ^ 1);
      asm volatile("cp.async.wait_group 1;" ::: "memory");
    } else {
      asm volatile("cp.async.wait_group 0;" ::: "memory");
    }
    __syncthreads();   // tile jt visible to all warps

    const float* Ks = sm + buf * KV_FLOATS;
    const float* Vs = sm + (2 + buf) * KV_FLOATS;

    // S[16,64] = Q_warp @ K^T
    float s[8][4] = {};
#pragma unroll
    for (int ks = 0; ks < 8; ks++) {
#pragma unroll
      for (int nf = 0; nf < 8; nf++) {
        float bfr[2];
        bfr[0] = Ks[(nf * 8 + g) * STR + ks * 8 + t];
        bfr[1] = Ks[(nf * 8 + g) * STR + ks * 8 + t + 4];
        mma_tf32(s[nf], qf[ks], bfr);
      }
    }

    // Causal mask (raw-score units)
    if (jt >= 2 * qb) {
      const int j0 = jt * BKV;
      const int r0 = q0 + wrow + g, r1 = r0 + 8;
#pragma unroll
      for (int nf = 0; nf < 8; nf++) {
        int c0 = j0 + nf * 8 + 2 * t, c1 = c0 + 1;
        if (c0 > r0) s[nf][0] = -1e30f;
        if (c1 > r0) s[nf][1] = -1e30f;
        if (c0 > r1) s[nf][2] = -1e30f;
        if (c1 > r1) s[nf][3] = -1e30f;
      }
    }

    // Online softmax (scale folded into exponent)
    float mx0 = -1e30f, mx1 = -1e30f;
#pragma unroll
    for (int nf = 0; nf < 8; nf++) {
      mx0 = fmaxf(mx0, fmaxf(s[nf][0], s[nf][1]));
      mx1 = fmaxf(mx1, fmaxf(s[nf][2], s[nf][3]));
    }
    mx0 = fmaxf(mx0, __shfl_xor_sync(0xffffffffu, mx0, 1));
    mx0 = fmaxf(mx0, __shfl_xor_sync(0xffffffffu, mx0, 2));
    mx1 = fmaxf(mx1, __shfl_xor_sync(0xffffffffu, mx1, 1));
    mx1 = fmaxf(mx1, __shfl_xor_sync(0xffffffffu, mx1, 2));

    float mn0 = fmaxf(m0, mx0), mn1 = fmaxf(m1, mx1);
    float scl0 = exp2f((m0 - mn0) * C), scl1 = exp2f((m1 - mn1) * C);
    m0 = mn0; m1 = mn1;

    float rs0 = 0.0f, rs1 = 0.0f;
#pragma unroll
    for (int nf = 0; nf < 8; nf++) {
      s[nf][0] = exp2f((s[nf][0] - mn0) * C);
      s[nf][1] = exp2f((s[nf][1] - mn0) * C);
      s[nf][2] = exp2f((s[nf][2] - mn1) * C);
      s[nf][3] = exp2f((s[nf][3] - mn1) * C);
      rs0 += s[nf][0] + s[nf][1];
      rs1 += s[nf][2] + s[nf][3];
      *(float2*)&Ps[(wrow + g) * STR + nf * 8 + 2 * t] =
          make_float2(to_tf32(s[nf][0]), to_tf32(s[nf][1]));
      *(float2*)&Ps[(wrow + g + 8) * STR + nf * 8 + 2 * t] =
          make_float2(to_tf32(s[nf][2]), to_tf32(s[nf][3]));
    }
    rs0 += __shfl_xor_sync(0xffffffffu, rs0, 1);
    rs0 += __shfl_xor_sync(0xffffffffu, rs0, 2);
    rs1 += __shfl_xor_sync(0xffffffffu, rs1, 1);
    rs1 += __shfl_xor_sync(0xffffffffu, rs1, 2);
    l0 = l0 * scl0 + rs0;
    l1 = l1 * scl1 + rs1;

#pragma unroll
    for (int nf = 0; nf < 8; nf++) {
      o[nf][0] *= scl0; o[nf][1] *= scl0;
      o[nf][2] *= scl1; o[nf][3] *= scl1;
    }
    __syncwarp();   // Ps rows: warp-local producer/consumer

    // O[16,64] += P_warp @ V
#pragma unroll
    for (int ks = 0; ks < 8; ks++) {
      float a[4];
      a[0] = Ps[(wrow + g) * STR + ks * 8 + t];
      a[1] = Ps[(wrow + g + 8) * STR + ks * 8 + t];
      a[2] = Ps[(wrow + g) * STR + ks * 8 + t + 4];
      a[3] = Ps[(wrow + g + 8) * STR + ks * 8 + t + 4];
#pragma unroll
      for (int nf = 0; nf < 8; nf++) {
        float bfr[2];
        bfr[0] = Vs[(ks * 8 + t) * STR + nf * 8 + g];
        bfr[1] = Vs[(ks * 8 + t + 4) * STR + nf * 8 + g];
        mma_tf32(o[nf], a, bfr);
      }
    }
    __syncthreads();   // all warps done with buf before next iter's KV_ISSUE
  }

  // Normalize, tf32-round (consumed by O-projection GEMM), write
  const float inv0 = 1.0f / l0, inv1 = 1.0f / l1;
  const int r0 = q0 + wrow + g, r1 = r0 + 8;
#pragma unroll
  for (int nf = 0; nf < 8; nf++) {
    int col = nf * 8 + 2 * t;
    *(float2*)(O + base + (size_t)r0 * DMODEL + col) =
        make_float2(to_tf32(o[nf][0] * inv0), to_tf32(o[nf][1] * inv0));
    *(float2*)(O + base + (size_t)r1 * DMODEL + col) =
        make_float2(to_tf32(o[nf][2] * inv1), to_tf32(o[nf][3] * inv1));
  }
#undef KV_ISSUE
}

// ---------------------------------------------------------------------------
extern "C" void kernel_launch(void* const* d_in, const int* in_sizes, int n_in,
                              void* d_out, int out_size) {
  const float* x  = (const float*)d_in[0];
  const float* Wq = (const float*)d_in[1];
  const float* bq = (const float*)d_in[2];
  const float* Wk = (const float*)d_in[3];
  const float* bk = (const float*)d_in[4];
  const float* Wv = (const float*)d_in[5];
  const float* bv = (const float*)d_in[6];
  const float* Wo = (const float*)d_in[7];
  const float* bo = (const float*)d_in[8];
  float* out = (float*)d_out;

  float *Qp, *Kp, *Vp, *Cp, *Ar, *W0, *W1, *W2, *W3;
  cudaGetSymbolAddress((void**)&Qp, g_Q);
  cudaGetSymbolAddress((void**)&Kp, g_K);
  cudaGetSymbolAddress((void**)&Vp, g_V);
  cudaGetSymbolAddress((void**)&Cp, g_CTX);
  cudaGetSymbolAddress((void**)&Ar, g_Ar);
  cudaGetSymbolAddress((void**)&W0, g_Wr0);
  cudaGetSymbolAddress((void**)&W1, g_Wr1);
  cudaGetSymbolAddress((void**)&W2, g_Wr2);
  cudaGetSymbolAddress((void**)&W3, g_Wr3);

  cudaFuncSetAttribute(flash_attn_tc_kernel,
                       cudaFuncAttributeMaxDynamicSharedMemorySize,
                       ATTN_SMEM_BYTES);
  cudaFuncSetAttribute(gemm_qkv_kernel,
                       cudaFuncAttributeMaxDynamicSharedMemorySize,
                       GT_SMEM_BYTES);
  cudaFuncSetAttribute(gemm_tf32_kernel,
                       cudaFuncAttributeMaxDynamicSharedMemorySize,
                       GT_SMEM_BYTES);

  // Single rounding pass for x + all weights
  const int ncvt = NA4 + 4 * NW4;
  cvt_all_kernel<<<ncvt / 256, 256>>>(x, Ar, Wq, W0, Wk, W1, Wv, W2, Wo, W3);

  // Fused Q/K/V projections
  dim3 qkv_grid(24, M_TOT / 128);
  gemm_qkv_kernel<<<qkv_grid, 256, GT_SMEM_BYTES>>>(
      Ar, W0, W1, W2, bq, bk, bv, Qp, Kp, Vp);

  dim3 attn_grid(S_LEN / BQ, NHEAD, BATCH);
  flash_attn_tc_kernel<<<attn_grid, 256, ATTN_SMEM_BYTES>>>(Qp, Kp, Vp, Cp);

  dim3 ggrid(DMODEL / 128, M_TOT / 128);
  gemm_tf32_kernel<<<ggrid, 256, GT_SMEM_BYTES>>>(Cp, W3, bo, out, 0);
}